// round 8
// baseline (speedup 1.0000x reference)
#include <cuda_runtime.h>
#include <cuda_bf16.h>
#include <cstdint>

#define H 128
#define NMAX 100000
#define EMAX 600000
#define TM 128
#define MLP_THREADS 256
#define ROWSTRIDE 72                        // u32 per row: 8-bank row skew -> conflict-free LDS.64
#define STAGE_OFF (4 * 128 * ROWSTRIDE)     // u32 offset of f32 stage buffer
#define MLP_SMEM (STAGE_OFF * 4 + 128 * 128 * 4)  // 147456 + 65536 = 212992 B

// Scratch (device globals: no allocation allowed)
__device__ __align__(16) float g_x[(size_t)NMAX * H];
__device__ __align__(16) float g_h[(size_t)NMAX * H];
// weight fragments: [layer][warp 8][img 4][nb 2][ks 8][lane 32][2] u32
__device__ __align__(16) uint32_t g_wfrag[3 * 8 * 4 * 2 * 8 * 32 * 2];
// CSR by dst (counting sort, built once per launch)
__device__ int g_cnt[NMAX];
__device__ int g_off[NMAX];
__device__ int g_fill[NMAX];
__device__ int g_cs[256];
__device__ int g_cbase[256];
__device__ int g_ssrc[EMAX];
__device__ __align__(16) float4 g_sattr[EMAX];

__device__ __forceinline__ uint32_t pack_bf16(float x, float y) {
    __nv_bfloat162 t = __floats2bfloat162_rn(x, y);
    return *(uint32_t*)&t;
}
// permuted pair index: pair j (cols 2j,2j+1) -> slot so that a0/a2 are adjacent
__device__ __forceinline__ int pidx(int j) {
    return ((j >> 3) << 3) + ((j & 3) << 1) + ((j >> 2) & 1);
}
__device__ __forceinline__ uint32_t smem_u32(const void* p) {
    uint32_t a;
    asm("{ .reg .u64 t; cvta.to.shared.u64 t, %1; cvt.u32.u64 %0, t; }" : "=r"(a) : "l"(p));
    return a;
}
__device__ __forceinline__ float silu_fast(float f) {
    float th;
    asm("tanh.approx.f32 %0, %1;" : "=f"(th) : "f"(0.5f * f));
    return f * fmaf(0.5f, th, 0.5f);
}

#define MMA_BF16(c, A0, A1, A2, A3, B0, B1)                                   \
    asm volatile("mma.sync.aligned.m16n8k16.row.col.f32.bf16.bf16.f32 "       \
                 "{%0,%1,%2,%3}, {%4,%5,%6,%7}, {%8,%9}, {%0,%1,%2,%3};"      \
                 : "+f"(c[0]), "+f"(c[1]), "+f"(c[2]), "+f"(c[3])             \
                 : "r"(A0), "r"(A1), "r"(A2), "r"(A3), "r"(B0), "r"(B1));

// ---------------------------------------------------------------------------
// CSR build: hist -> parallel chunk reduction -> chunk scan -> in-chunk scan
// -> scatter src+attr into dst-sorted order.
// ---------------------------------------------------------------------------
__global__ void k_zero(int n) {
    int i = blockIdx.x * blockDim.x + threadIdx.x;
    if (i < n) { g_cnt[i] = 0; g_fill[i] = 0; }
}
__global__ void k_hist(const int* __restrict__ ei, int E) {
    int e = blockIdx.x * blockDim.x + threadIdx.x;
    if (e < E) atomicAdd(&g_cnt[ei[E + e]], 1);
}
// one block (256 thr) per 512-chunk: parallel tree reduction
__global__ void k_chunkred(int n) {
    __shared__ int sh[256];
    int c = blockIdx.x, tid = threadIdx.x;
    int idx = c * 512 + tid;
    int v = 0;
    if (idx < n) v = g_cnt[idx];
    if (idx + 256 < n && (idx + 256) < (c + 1) * 512) v += g_cnt[idx + 256];
    sh[tid] = v;
    __syncthreads();
    for (int o = 128; o > 0; o >>= 1) {
        if (tid < o) sh[tid] += sh[tid + o];
        __syncthreads();
    }
    if (tid == 0) g_cs[c] = sh[0];
}
__global__ void k_chunkscan(int nch) {
    __shared__ int sh[256];
    int tid = threadIdx.x;
    int v = (tid < nch) ? g_cs[tid] : 0;
    sh[tid] = v;
    __syncthreads();
    for (int o = 1; o < 256; o <<= 1) {
        int t = (tid >= o) ? sh[tid - o] : 0;
        __syncthreads();
        sh[tid] += t;
        __syncthreads();
    }
    g_cbase[tid] = sh[tid] - v;    // exclusive
}
__global__ void k_offsets(int n) {
    __shared__ int sh[512];
    int c = blockIdx.x, tid = threadIdx.x;
    int idx = c * 512 + tid;
    int v = (idx < n) ? g_cnt[idx] : 0;
    sh[tid] = v;
    __syncthreads();
    for (int o = 1; o < 512; o <<= 1) {
        int t = (tid >= o) ? sh[tid - o] : 0;
        __syncthreads();
        sh[tid] += t;
        __syncthreads();
    }
    if (idx < n) g_off[idx] = g_cbase[c] + sh[tid] - v;
}
__global__ void k_scatter(const int* __restrict__ ei,
                          const float* __restrict__ edge_attr, int E) {
    int e = blockIdx.x * blockDim.x + threadIdx.x;
    if (e >= E) return;
    int d = ei[E + e];
    int p = g_off[d] + atomicAdd(&g_fill[d], 1);
    g_ssrc[p] = ei[e];
    g_sattr[p] = ((const float4*)edge_attr)[e];
}

// ---------------------------------------------------------------------------
// Weight prep: split W1/W2 (f32 [k][n]) into bf16 hi/lo mma B-fragments,
// laid out exactly in the per-warp register-load order.
// ---------------------------------------------------------------------------
__global__ void wprep_kernel(const float* __restrict__ W1,
                             const float* __restrict__ W2) {
    int idx = blockIdx.x * blockDim.x + threadIdx.x;
    if (idx >= 3 * 8 * 4 * 2 * 8 * 32 * 2) return;
    int r    = idx & 1;
    int lane = (idx >> 1) & 31;
    int ks   = (idx >> 6) & 7;
    int nb   = (idx >> 9) & 1;
    int img  = (idx >> 10) & 3;
    int w    = (idx >> 12) & 7;
    int l    = idx >> 15;
    int gid = lane >> 2, tg = lane & 3;
    int mat = img >> 1, hl = img & 1;
    int n  = w * 16 + nb * 8 + gid;
    int k0 = ks * 16 + tg * 2 + r * 8;
    const float* W = (mat ? W2 : W1) + (size_t)l * H * H;
    float v0 = W[k0 * H + n];
    float v1 = W[(k0 + 1) * H + n];
    __nv_bfloat16 h0 = __float2bfloat16(v0);
    __nv_bfloat16 h1 = __float2bfloat16(v1);
    float o0 = hl ? (v0 - __bfloat162float(h0)) : __bfloat162float(h0);
    float o1 = hl ? (v1 - __bfloat162float(h1)) : __bfloat162float(h1);
    g_wfrag[idx] = pack_bf16(o0, o1);
}

// ---------------------------------------------------------------------------
// Embedding gather (x only; h is produced by the CSR edge kernel)
// ---------------------------------------------------------------------------
__global__ void embed_kernel(const float* __restrict__ emb,
                             const int* __restrict__ z,
                             float* __restrict__ x, int n) {
    int i = blockIdx.x * blockDim.x + threadIdx.x;
    if (i >= n * 32) return;
    int node = i >> 5;
    int c = i & 31;
    ((float4*)x)[i] = ((const float4*)emb)[(size_t)z[node] * 32 + c];
}

// ---------------------------------------------------------------------------
// CSR edge kernel: one warp per destination node, zero atomics.
//   h[d] = x[d] + sum_{e in dst==d} relu(x[src_e] + ea_e @ We + be)
// ---------------------------------------------------------------------------
__global__ void edge_csr_kernel(const float* __restrict__ x,
                                float* __restrict__ h,
                                const float* __restrict__ We,
                                const float* __restrict__ be,
                                int n) {
    __shared__ float Wes[4 * H];
    __shared__ float bes[H];
    int tid = threadIdx.x;
    for (int i = tid; i < 4 * H; i += blockDim.x) Wes[i] = We[i];
    for (int i = tid; i < H; i += blockDim.x) bes[i] = be[i];
    __syncthreads();

    int lane = tid & 31;
    int node = blockIdx.x * (blockDim.x >> 5) + (tid >> 5);
    if (node >= n) return;

    float4 w0 = ((const float4*)Wes)[0 * 32 + lane];
    float4 w1 = ((const float4*)Wes)[1 * 32 + lane];
    float4 w2 = ((const float4*)Wes)[2 * 32 + lane];
    float4 w3 = ((const float4*)Wes)[3 * 32 + lane];
    float4 bb = ((const float4*)bes)[lane];

    float4 acc = ((const float4*)x)[(size_t)node * 32 + lane];  // (1+eps)*x, eps=0
    int e = g_off[node];
    int end = e + g_cnt[node];

    #pragma unroll 1
    for (; e < end; e += 4) {
        int m = end - e; if (m > 4) m = 4;
        int s[4];
        float4 ea[4], xv[4];
        #pragma unroll
        for (int j = 0; j < 4; j++)
            if (j < m) s[j] = g_ssrc[e + j];
        #pragma unroll
        for (int j = 0; j < 4; j++)
            if (j < m) ea[j] = g_sattr[e + j];
        #pragma unroll
        for (int j = 0; j < 4; j++)
            if (j < m) xv[j] = ((const float4*)x)[(size_t)s[j] * 32 + lane];
        #pragma unroll
        for (int j = 0; j < 4; j++) {
            if (j >= m) break;
            float m0 = xv[j].x + bb.x + ea[j].x * w0.x + ea[j].y * w1.x + ea[j].z * w2.x + ea[j].w * w3.x;
            float m1 = xv[j].y + bb.y + ea[j].x * w0.y + ea[j].y * w1.y + ea[j].z * w2.y + ea[j].w * w3.y;
            float m2 = xv[j].z + bb.z + ea[j].x * w0.z + ea[j].y * w1.z + ea[j].z * w2.z + ea[j].w * w3.z;
            float m3 = xv[j].w + bb.w + ea[j].x * w0.w + ea[j].y * w1.w + ea[j].z * w2.w + ea[j].w * w3.w;
            acc.x += fmaxf(m0, 0.f);
            acc.y += fmaxf(m1, 0.f);
            acc.z += fmaxf(m2, 0.f);
            acc.w += fmaxf(m3, 0.f);
        }
    }
    ((float4*)h)[(size_t)node * 32 + lane] = acc;   // plain coalesced store
}

// ---------------------------------------------------------------------------
// Fused 2-layer MLP via mma.sync bf16x3: D = Ah*Bh + Al*Bh + Ah*Bl
// Persistent CTAs, 128-row tiles, cp.async-prefetched stage buffer,
// tanh-based silu, conflict-free smem layout (ROWSTRIDE=72).   [R5 version]
// ---------------------------------------------------------------------------
__global__ void __launch_bounds__(MLP_THREADS, 1)
mlp_kernel(const float* __restrict__ h_in,
           const uint32_t* __restrict__ wfrag,
           const float* __restrict__ b1, const float* __restrict__ b2,
           float* __restrict__ x_out, int n) {
    extern __shared__ __align__(16) uint32_t sm[];
    uint32_t* Hs_hi = sm;
    uint32_t* Hs_lo = sm + 128 * ROWSTRIDE;
    uint32_t* Ts_hi = sm + 2 * 128 * ROWSTRIDE;
    uint32_t* Ts_lo = sm + 3 * 128 * ROWSTRIDE;
    float* stage = (float*)(sm + STAGE_OFF);          // 128x128 f32
    uint32_t stage_b = smem_u32(stage);

    int tid = threadIdx.x, w = tid >> 5, lane = tid & 31;
    int gid = lane >> 2, tg = lane & 3;

    // this warp's weight fragments (128 u32)
    uint2 wB[4][2][8];
    {
        const uint2* wp = (const uint2*)wfrag + (size_t)w * 4 * 2 * 8 * 32;
        #pragma unroll
        for (int img = 0; img < 4; img++)
            #pragma unroll
            for (int nb = 0; nb < 2; nb++)
                #pragma unroll
                for (int ks = 0; ks < 8; ks++)
                    wB[img][nb][ks] = wp[(((img * 2) + nb) * 8 + ks) * 32 + lane];
    }
    float2 b1v[2], b2v[2];
    #pragma unroll
    for (int nb = 0; nb < 2; nb++) {
        b1v[nb] = *(const float2*)(b1 + 16 * w + 8 * nb + 2 * tg);
        b2v[nb] = *(const float2*)(b2 + 16 * w + 8 * nb + 2 * tg);
    }

    int ntiles = (n + TM - 1) / TM;

    // prefetch first tile
    {
        int t = blockIdx.x;
        if (t < ntiles) {
            int row0 = t * TM;
            #pragma unroll
            for (int it = 0; it < 16; it++) {
                int i = tid + it * MLP_THREADS;
                int grow = row0 + (i >> 5);
                if (grow < n) {
                    uint32_t sa = stage_b + i * 16;
                    const float* gp = h_in + (size_t)grow * H + (i & 31) * 4;
                    asm volatile("cp.async.ca.shared.global [%0], [%1], 16;"
                                 :: "r"(sa), "l"(gp));
                }
            }
        }
        asm volatile("cp.async.commit_group;");
    }

    for (int t = blockIdx.x; t < ntiles; t += gridDim.x) {
        int row0 = t * TM;
        asm volatile("cp.async.wait_group 0;" ::: "memory");
        __syncthreads();

        // ---- convert stage -> bf16 hi/lo smem ----
        #pragma unroll 4
        for (int it = 0; it < 16; it++) {
            int i = tid + it * MLP_THREADS;
            int row = i >> 5;
            int c4 = i & 31;
            float4 v = make_float4(0.f, 0.f, 0.f, 0.f);
            if (row0 + row < n) v = ((const float4*)stage)[i];
            __nv_bfloat16 hx = __float2bfloat16(v.x), hy = __float2bfloat16(v.y);
            __nv_bfloat16 hz = __float2bfloat16(v.z), hw = __float2bfloat16(v.w);
            int base = row * ROWSTRIDE;
            int p0 = pidx(2 * c4), p1 = pidx(2 * c4 + 1);
            Hs_hi[base + p0] = pack_bf16(__bfloat162float(hx), __bfloat162float(hy));
            Hs_hi[base + p1] = pack_bf16(__bfloat162float(hz), __bfloat162float(hw));
            Hs_lo[base + p0] = pack_bf16(v.x - __bfloat162float(hx), v.y - __bfloat162float(hy));
            Hs_lo[base + p1] = pack_bf16(v.z - __bfloat162float(hz), v.w - __bfloat162float(hw));
        }
        __syncthreads();

        // ---- prefetch next tile (stage now free) ----
        {
            int tn = t + gridDim.x;
            if (tn < ntiles) {
                int r0n = tn * TM;
                #pragma unroll
                for (int it = 0; it < 16; it++) {
                    int i = tid + it * MLP_THREADS;
                    int grow = r0n + (i >> 5);
                    if (grow < n) {
                        uint32_t sa = stage_b + i * 16;
                        const float* gp = h_in + (size_t)grow * H + (i & 31) * 4;
                        asm volatile("cp.async.ca.shared.global [%0], [%1], 16;"
                                     :: "r"(sa), "l"(gp));
                    }
                }
            }
            asm volatile("cp.async.commit_group;");
        }

        // ---- GEMM1: T = silu(H @ W1 + b1) -> Ts ----
        #pragma unroll 1
        for (int mb = 0; mb < 8; mb++) {
            float acc[2][4] = {{0.f, 0.f, 0.f, 0.f}, {0.f, 0.f, 0.f, 0.f}};
            int ra = (mb * 16 + gid) * ROWSTRIDE;
            int rb = ra + 8 * ROWSTRIDE;
            #pragma unroll
            for (int ks = 0; ks < 8; ks++) {
                uint2 ah  = *(const uint2*)(Hs_hi + ra + ks * 8 + tg * 2);
                uint2 ahb = *(const uint2*)(Hs_hi + rb + ks * 8 + tg * 2);
                uint2 al  = *(const uint2*)(Hs_lo + ra + ks * 8 + tg * 2);
                uint2 alb = *(const uint2*)(Hs_lo + rb + ks * 8 + tg * 2);
                #pragma unroll
                for (int nb = 0; nb < 2; nb++) {
                    uint2 bh = wB[0][nb][ks];
                    uint2 bl = wB[1][nb][ks];
                    MMA_BF16(acc[nb], ah.x, ahb.x, ah.y, ahb.y, bh.x, bh.y);
                    MMA_BF16(acc[nb], al.x, alb.x, al.y, alb.y, bh.x, bh.y);
                    MMA_BF16(acc[nb], ah.x, ahb.x, ah.y, ahb.y, bl.x, bl.y);
                }
            }
            int sa = (mb * 16 + gid) * ROWSTRIDE + 8 * w + 2 * tg;
            int sb = sa + 8 * ROWSTRIDE;
            #pragma unroll
            for (int nb = 0; nb < 2; nb++) {
                float f0 = silu_fast(acc[nb][0] + b1v[nb].x);
                float f1 = silu_fast(acc[nb][1] + b1v[nb].y);
                float f2 = silu_fast(acc[nb][2] + b1v[nb].x);
                float f3 = silu_fast(acc[nb][3] + b1v[nb].y);
                __nv_bfloat16 h0 = __float2bfloat16(f0), h1 = __float2bfloat16(f1);
                __nv_bfloat16 h2 = __float2bfloat16(f2), h3 = __float2bfloat16(f3);
                Ts_hi[sa + nb] = pack_bf16(__bfloat162float(h0), __bfloat162float(h1));
                Ts_hi[sb + nb] = pack_bf16(__bfloat162float(h2), __bfloat162float(h3));
                Ts_lo[sa + nb] = pack_bf16(f0 - __bfloat162float(h0), f1 - __bfloat162float(h1));
                Ts_lo[sb + nb] = pack_bf16(f2 - __bfloat162float(h2), f3 - __bfloat162float(h3));
            }
        }
        __syncthreads();

        // ---- GEMM2: out = T @ W2 + b2 -> gmem ----
        #pragma unroll 1
        for (int mb = 0; mb < 8; mb++) {
            float acc[2][4] = {{0.f, 0.f, 0.f, 0.f}, {0.f, 0.f, 0.f, 0.f}};
            int ra = (mb * 16 + gid) * ROWSTRIDE;
            int rb = ra + 8 * ROWSTRIDE;
            #pragma unroll
            for (int ks = 0; ks < 8; ks++) {
                uint2 ah  = *(const uint2*)(Ts_hi + ra + ks * 8 + tg * 2);
                uint2 ahb = *(const uint2*)(Ts_hi + rb + ks * 8 + tg * 2);
                uint2 al  = *(const uint2*)(Ts_lo + ra + ks * 8 + tg * 2);
                uint2 alb = *(const uint2*)(Ts_lo + rb + ks * 8 + tg * 2);
                #pragma unroll
                for (int nb = 0; nb < 2; nb++) {
                    uint2 bh = wB[2][nb][ks];
                    uint2 bl = wB[3][nb][ks];
                    MMA_BF16(acc[nb], ah.x, ahb.x, ah.y, ahb.y, bh.x, bh.y);
                    MMA_BF16(acc[nb], al.x, alb.x, al.y, alb.y, bh.x, bh.y);
                    MMA_BF16(acc[nb], ah.x, ahb.x, ah.y, ahb.y, bl.x, bl.y);
                }
            }
            int r0 = row0 + mb * 16 + gid;
            int r1 = r0 + 8;
            #pragma unroll
            for (int nb = 0; nb < 2; nb++) {
                int col = 16 * w + 8 * nb + 2 * tg;
                if (r0 < n) {
                    float2 o0 = make_float2(acc[nb][0] + b2v[nb].x,
                                            acc[nb][1] + b2v[nb].y);
                    *(float2*)(x_out + (size_t)r0 * H + col) = o0;
                }
                if (r1 < n) {
                    float2 o1 = make_float2(acc[nb][2] + b2v[nb].x,
                                            acc[nb][3] + b2v[nb].y);
                    *(float2*)(x_out + (size_t)r1 * H + col) = o1;
                }
            }
        }
        __syncthreads();
    }
}

// batch_vec -> float tail of the output
__global__ void batch_kernel(const int* __restrict__ bv, float* __restrict__ out, int n) {
    int i = blockIdx.x * blockDim.x + threadIdx.x;
    if (i < n) out[i] = (float)bv[i];
}

extern "C" void kernel_launch(void* const* d_in, const int* in_sizes, int n_in,
                              void* d_out, int out_size) {
    const float* emb       = (const float*)d_in[0];
    const float* We        = (const float*)d_in[1];
    const float* be        = (const float*)d_in[2];
    const float* W1        = (const float*)d_in[3];
    const float* b1        = (const float*)d_in[4];
    const float* W2        = (const float*)d_in[5];
    const float* b2        = (const float*)d_in[6];
    const float* edge_attr = (const float*)d_in[7];
    const int*   z         = (const int*)d_in[8];
    const int*   ei        = (const int*)d_in[9];
    const int*   bv        = (const int*)d_in[10];

    int n = in_sizes[8];
    int E = in_sizes[9] / 2;
    float* out = (float*)d_out;
    int nch = (n + 511) / 512;

    float *gx, *gh;
    uint32_t* gwf;
    cudaGetSymbolAddress((void**)&gx, g_x);
    cudaGetSymbolAddress((void**)&gh, g_h);
    cudaGetSymbolAddress((void**)&gwf, g_wfrag);

    cudaFuncSetAttribute(mlp_kernel, cudaFuncAttributeMaxDynamicSharedMemorySize,
                         MLP_SMEM);

    // CSR build (once per launch)
    k_zero<<<(n + 255) / 256, 256>>>(n);
    k_hist<<<(E + 255) / 256, 256>>>(ei, E);
    k_chunkred<<<nch, 256>>>(n);
    k_chunkscan<<<1, 256>>>(nch);
    k_offsets<<<nch, 512>>>(n);
    k_scatter<<<(E + 255) / 256, 256>>>(ei, edge_attr, E);

    wprep_kernel<<<(3 * 8 * 4 * 2 * 8 * 32 * 2 + 255) / 256, 256>>>(W1, W2);
    embed_kernel<<<(n * 32 + 255) / 256, 256>>>(emb, z, gx, n);

    for (int l = 0; l < 3; l++) {
        edge_csr_kernel<<<(n + 7) / 8, 256>>>(gx, gh,
                                              We + (size_t)l * 4 * H,
                                              be + (size_t)l * H, n);
        bool last = (l == 2);
        mlp_kernel<<<148, MLP_THREADS, MLP_SMEM>>>(
            gh,
            gwf + (size_t)l * 8 * 4 * 2 * 8 * 32 * 2,
            b1 + (size_t)l * H, b2 + (size_t)l * H,
            last ? out : gx,
            n);
    }

    if (out_size >= n * H + n) {
        batch_kernel<<<(n + 255) / 256, 256>>>(bv, out + (size_t)n * H, n);
    }
}

// round 9
// speedup vs baseline: 1.2461x; 1.2461x over previous
#include <cuda_runtime.h>
#include <cuda_bf16.h>
#include <cstdint>

#define H 128
#define NMAX 100000
#define TM 128
#define MLP_THREADS 256
#define ROWSTRIDE 72                        // u32 per row: 8-bank row skew -> conflict-free LDS.64
#define STAGE_OFF (4 * 128 * ROWSTRIDE)     // u32 offset of f32 stage buffer
#define MLP_SMEM (STAGE_OFF * 4 + 128 * 128 * 4)  // 147456 + 65536 = 212992 B

// Scratch (device globals: no allocation allowed)
__device__ __align__(16) float g_x[(size_t)NMAX * H];
__device__ __align__(16) float g_h[(size_t)NMAX * H];
// weight fragments: [layer][warp 8][img 4][nb 2][ks 8][lane 32][2] u32
__device__ __align__(16) uint32_t g_wfrag[3 * 8 * 4 * 2 * 8 * 32 * 2];

__device__ __forceinline__ uint32_t pack_bf16(float x, float y) {
    __nv_bfloat162 t = __floats2bfloat162_rn(x, y);
    return *(uint32_t*)&t;
}
// permuted pair index: pair j (cols 2j,2j+1) -> slot so that a0/a2 are adjacent
__device__ __forceinline__ int pidx(int j) {
    return ((j >> 3) << 3) + ((j & 3) << 1) + ((j >> 2) & 1);
}
__device__ __forceinline__ uint32_t smem_u32(const void* p) {
    uint32_t a;
    asm("{ .reg .u64 t; cvta.to.shared.u64 t, %1; cvt.u32.u64 %0, t; }" : "=r"(a) : "l"(p));
    return a;
}
__device__ __forceinline__ float silu_fast(float f) {
    float th;
    asm("tanh.approx.f32 %0, %1;" : "=f"(th) : "f"(0.5f * f));
    return f * fmaf(0.5f, th, 0.5f);
}

#define MMA_BF16(c, A0, A1, A2, A3, B0, B1)                                   \
    asm volatile("mma.sync.aligned.m16n8k16.row.col.f32.bf16.bf16.f32 "       \
                 "{%0,%1,%2,%3}, {%4,%5,%6,%7}, {%8,%9}, {%0,%1,%2,%3};"      \
                 : "+f"(c[0]), "+f"(c[1]), "+f"(c[2]), "+f"(c[3])             \
                 : "r"(A0), "r"(A1), "r"(A2), "r"(A3), "r"(B0), "r"(B1));

// ---------------------------------------------------------------------------
// Weight prep: split W1/W2 (f32 [k][n]) into bf16 hi/lo mma B-fragments,
// laid out exactly in the per-warp register-load order.
// ---------------------------------------------------------------------------
__global__ void wprep_kernel(const float* __restrict__ W1,
                             const float* __restrict__ W2) {
    int idx = blockIdx.x * blockDim.x + threadIdx.x;
    if (idx >= 3 * 8 * 4 * 2 * 8 * 32 * 2) return;
    int r    = idx & 1;
    int lane = (idx >> 1) & 31;
    int ks   = (idx >> 6) & 7;
    int nb   = (idx >> 9) & 1;
    int img  = (idx >> 10) & 3;
    int w    = (idx >> 12) & 7;
    int l    = idx >> 15;
    int gid = lane >> 2, tg = lane & 3;
    int mat = img >> 1, hl = img & 1;
    int n  = w * 16 + nb * 8 + gid;
    int k0 = ks * 16 + tg * 2 + r * 8;
    const float* W = (mat ? W2 : W1) + (size_t)l * H * H;
    float v0 = W[k0 * H + n];
    float v1 = W[(k0 + 1) * H + n];
    __nv_bfloat16 h0 = __float2bfloat16(v0);
    __nv_bfloat16 h1 = __float2bfloat16(v1);
    float o0 = hl ? (v0 - __bfloat162float(h0)) : __bfloat162float(h0);
    float o1 = hl ? (v1 - __bfloat162float(h1)) : __bfloat162float(h1);
    g_wfrag[idx] = pack_bf16(o0, o1);
}

// ---------------------------------------------------------------------------
// Embedding gather: x[i] = emb[z[i]], h[i] = x[i]
// ---------------------------------------------------------------------------
__global__ void embed_kernel(const float* __restrict__ emb,
                             const int* __restrict__ z,
                             float* __restrict__ x, float* __restrict__ h,
                             int n) {
    int i = blockIdx.x * blockDim.x + threadIdx.x;
    if (i >= n * 32) return;
    int node = i >> 5;
    int c = i & 31;
    float4 v = ((const float4*)emb)[(size_t)z[node] * 32 + c];
    ((float4*)x)[i] = v;
    ((float4*)h)[i] = v;
}

// ---------------------------------------------------------------------------
// Edge/message kernel: one warp per 4 edges (pipelined), lane = 4 channels.
//   e = edge_attr @ We + be ; m = relu(x[src] + e) ; h[dst] += m (red.v4)
// ---------------------------------------------------------------------------
__global__ void edge_kernel(const float* __restrict__ x,
                            float* __restrict__ h,
                            const float* __restrict__ edge_attr,
                            const int* __restrict__ ei,
                            const float* __restrict__ We,
                            const float* __restrict__ be,
                            int E) {
    __shared__ float Wes[4 * H];
    __shared__ float bes[H];
    int tid = threadIdx.x;
    for (int i = tid; i < 4 * H; i += blockDim.x) Wes[i] = We[i];
    for (int i = tid; i < H; i += blockDim.x) bes[i] = be[i];
    __syncthreads();

    int lane = tid & 31;
    int warp = blockIdx.x * (blockDim.x >> 5) + (tid >> 5);
    int nwarps = gridDim.x * (blockDim.x >> 5);

    float4 w0 = ((const float4*)Wes)[0 * 32 + lane];
    float4 w1 = ((const float4*)Wes)[1 * 32 + lane];
    float4 w2 = ((const float4*)Wes)[2 * 32 + lane];
    float4 w3 = ((const float4*)Wes)[3 * 32 + lane];
    float4 bb = ((const float4*)bes)[lane];

    int stride = nwarps * 4;
    #pragma unroll 1
    for (int e0 = warp * 4; e0 < E; e0 += stride) {
        int ne = E - e0; if (ne > 4) ne = 4;
        int s[4], d[4];
        float4 ea[4], xv[4];
        #pragma unroll
        for (int j = 0; j < 4; j++)
            if (j < ne) { s[j] = ei[e0 + j]; d[j] = ei[E + e0 + j]; }
        #pragma unroll
        for (int j = 0; j < 4; j++)
            if (j < ne) ea[j] = ((const float4*)edge_attr)[e0 + j];
        #pragma unroll
        for (int j = 0; j < 4; j++)
            if (j < ne) xv[j] = ((const float4*)x)[(size_t)s[j] * 32 + lane];
        #pragma unroll
        for (int j = 0; j < 4; j++) {
            if (j >= ne) break;
            float m0 = xv[j].x + bb.x + ea[j].x * w0.x + ea[j].y * w1.x + ea[j].z * w2.x + ea[j].w * w3.x;
            float m1 = xv[j].y + bb.y + ea[j].x * w0.y + ea[j].y * w1.y + ea[j].z * w2.y + ea[j].w * w3.y;
            float m2 = xv[j].z + bb.z + ea[j].x * w0.z + ea[j].y * w1.z + ea[j].z * w2.z + ea[j].w * w3.z;
            float m3 = xv[j].w + bb.w + ea[j].x * w0.w + ea[j].y * w1.w + ea[j].z * w2.w + ea[j].w * w3.w;
            m0 = fmaxf(m0, 0.f); m1 = fmaxf(m1, 0.f);
            m2 = fmaxf(m2, 0.f); m3 = fmaxf(m3, 0.f);
            float* dptr = h + (size_t)d[j] * H + lane * 4;
            asm volatile("red.global.add.v4.f32 [%0], {%1,%2,%3,%4};"
                         :: "l"(dptr), "f"(m0), "f"(m1), "f"(m2), "f"(m3)
                         : "memory");
        }
    }
}

// ---------------------------------------------------------------------------
// Fused 2-layer MLP via mma.sync bf16x3: D = Ah*Bh + Al*Bh + Ah*Bl
// Persistent CTAs, 128-row tiles, cp.async prefetch, tanh silu,
// conflict-free smem (ROWSTRIDE=72). Dual-mb accumulator chains for
// MMA-latency hiding (8 independent chains per SMSP).
// ---------------------------------------------------------------------------
__global__ void __launch_bounds__(MLP_THREADS, 1)
mlp_kernel(const float* __restrict__ h_in,
           const uint32_t* __restrict__ wfrag,
           const float* __restrict__ b1, const float* __restrict__ b2,
           float* __restrict__ x_out, float* __restrict__ h_out, int n) {
    extern __shared__ __align__(16) uint32_t sm[];
    uint32_t* Hs_hi = sm;
    uint32_t* Hs_lo = sm + 128 * ROWSTRIDE;
    uint32_t* Ts_hi = sm + 2 * 128 * ROWSTRIDE;
    uint32_t* Ts_lo = sm + 3 * 128 * ROWSTRIDE;
    float* stage = (float*)(sm + STAGE_OFF);          // 128x128 f32
    uint32_t stage_b = smem_u32(stage);

    int tid = threadIdx.x, w = tid >> 5, lane = tid & 31;
    int gid = lane >> 2, tg = lane & 3;

    // this warp's weight fragments (128 u32)
    uint2 wB[4][2][8];
    {
        const uint2* wp = (const uint2*)wfrag + (size_t)w * 4 * 2 * 8 * 32;
        #pragma unroll
        for (int img = 0; img < 4; img++)
            #pragma unroll
            for (int nb = 0; nb < 2; nb++)
                #pragma unroll
                for (int ks = 0; ks < 8; ks++)
                    wB[img][nb][ks] = wp[(((img * 2) + nb) * 8 + ks) * 32 + lane];
    }
    float2 b1v[2], b2v[2];
    #pragma unroll
    for (int nb = 0; nb < 2; nb++) {
        b1v[nb] = *(const float2*)(b1 + 16 * w + 8 * nb + 2 * tg);
        b2v[nb] = *(const float2*)(b2 + 16 * w + 8 * nb + 2 * tg);
    }

    int ntiles = (n + TM - 1) / TM;

    // prefetch first tile
    {
        int t = blockIdx.x;
        if (t < ntiles) {
            int row0 = t * TM;
            #pragma unroll
            for (int it = 0; it < 16; it++) {
                int i = tid + it * MLP_THREADS;
                int grow = row0 + (i >> 5);
                if (grow < n) {
                    uint32_t sa = stage_b + i * 16;
                    const float* gp = h_in + (size_t)grow * H + (i & 31) * 4;
                    asm volatile("cp.async.ca.shared.global [%0], [%1], 16;"
                                 :: "r"(sa), "l"(gp));
                }
            }
        }
        asm volatile("cp.async.commit_group;");
    }

    for (int t = blockIdx.x; t < ntiles; t += gridDim.x) {
        int row0 = t * TM;
        asm volatile("cp.async.wait_group 0;" ::: "memory");
        __syncthreads();

        // ---- convert stage -> bf16 hi/lo smem ----
        #pragma unroll 4
        for (int it = 0; it < 16; it++) {
            int i = tid + it * MLP_THREADS;
            int row = i >> 5;
            int c4 = i & 31;
            float4 v = make_float4(0.f, 0.f, 0.f, 0.f);
            if (row0 + row < n) v = ((const float4*)stage)[i];
            __nv_bfloat16 hx = __float2bfloat16(v.x), hy = __float2bfloat16(v.y);
            __nv_bfloat16 hz = __float2bfloat16(v.z), hw = __float2bfloat16(v.w);
            int base = row * ROWSTRIDE;
            int p0 = pidx(2 * c4), p1 = pidx(2 * c4 + 1);
            Hs_hi[base + p0] = pack_bf16(__bfloat162float(hx), __bfloat162float(hy));
            Hs_hi[base + p1] = pack_bf16(__bfloat162float(hz), __bfloat162float(hw));
            Hs_lo[base + p0] = pack_bf16(v.x - __bfloat162float(hx), v.y - __bfloat162float(hy));
            Hs_lo[base + p1] = pack_bf16(v.z - __bfloat162float(hz), v.w - __bfloat162float(hw));
        }
        __syncthreads();

        // ---- prefetch next tile (stage now free) ----
        {
            int tn = t + gridDim.x;
            if (tn < ntiles) {
                int r0n = tn * TM;
                #pragma unroll
                for (int it = 0; it < 16; it++) {
                    int i = tid + it * MLP_THREADS;
                    int grow = r0n + (i >> 5);
                    if (grow < n) {
                        uint32_t sa = stage_b + i * 16;
                        const float* gp = h_in + (size_t)grow * H + (i & 31) * 4;
                        asm volatile("cp.async.ca.shared.global [%0], [%1], 16;"
                                     :: "r"(sa), "l"(gp));
                    }
                }
            }
            asm volatile("cp.async.commit_group;");
        }

        // ---- GEMM1: T = silu(H @ W1 + b1) -> Ts  (dual-mb) ----
        #pragma unroll 1
        for (int mb = 0; mb < 8; mb += 2) {
            float acc[2][2][4];   // [mbi][nb][4]
            #pragma unroll
            for (int mi = 0; mi < 2; mi++)
                #pragma unroll
                for (int nb = 0; nb < 2; nb++)
                    #pragma unroll
                    for (int q = 0; q < 4; q++) acc[mi][nb][q] = 0.f;
            int ra0 = (mb * 16 + gid) * ROWSTRIDE;
            int rb0 = ra0 + 8 * ROWSTRIDE;
            int ra1 = ra0 + 16 * ROWSTRIDE;
            int rb1 = ra1 + 8 * ROWSTRIDE;
            #pragma unroll
            for (int ks = 0; ks < 8; ks++) {
                uint2 ah0  = *(const uint2*)(Hs_hi + ra0 + ks * 8 + tg * 2);
                uint2 ahb0 = *(const uint2*)(Hs_hi + rb0 + ks * 8 + tg * 2);
                uint2 al0  = *(const uint2*)(Hs_lo + ra0 + ks * 8 + tg * 2);
                uint2 alb0 = *(const uint2*)(Hs_lo + rb0 + ks * 8 + tg * 2);
                uint2 ah1  = *(const uint2*)(Hs_hi + ra1 + ks * 8 + tg * 2);
                uint2 ahb1 = *(const uint2*)(Hs_hi + rb1 + ks * 8 + tg * 2);
                uint2 al1  = *(const uint2*)(Hs_lo + ra1 + ks * 8 + tg * 2);
                uint2 alb1 = *(const uint2*)(Hs_lo + rb1 + ks * 8 + tg * 2);
                #pragma unroll
                for (int nb = 0; nb < 2; nb++) {
                    uint2 bh = wB[0][nb][ks];
                    uint2 bl = wB[1][nb][ks];
                    MMA_BF16(acc[0][nb], ah0.x, ahb0.x, ah0.y, ahb0.y, bh.x, bh.y);
                    MMA_BF16(acc[1][nb], ah1.x, ahb1.x, ah1.y, ahb1.y, bh.x, bh.y);
                    MMA_BF16(acc[0][nb], al0.x, alb0.x, al0.y, alb0.y, bh.x, bh.y);
                    MMA_BF16(acc[1][nb], al1.x, alb1.x, al1.y, alb1.y, bh.x, bh.y);
                    MMA_BF16(acc[0][nb], ah0.x, ahb0.x, ah0.y, ahb0.y, bl.x, bl.y);
                    MMA_BF16(acc[1][nb], ah1.x, ahb1.x, ah1.y, ahb1.y, bl.x, bl.y);
                }
            }
            #pragma unroll
            for (int mi = 0; mi < 2; mi++) {
                int sa = ((mb + mi) * 16 + gid) * ROWSTRIDE + 8 * w + 2 * tg;
                int sb = sa + 8 * ROWSTRIDE;
                #pragma unroll
                for (int nb = 0; nb < 2; nb++) {
                    float f0 = silu_fast(acc[mi][nb][0] + b1v[nb].x);
                    float f1 = silu_fast(acc[mi][nb][1] + b1v[nb].y);
                    float f2 = silu_fast(acc[mi][nb][2] + b1v[nb].x);
                    float f3 = silu_fast(acc[mi][nb][3] + b1v[nb].y);
                    __nv_bfloat16 h0 = __float2bfloat16(f0), h1 = __float2bfloat16(f1);
                    __nv_bfloat16 h2 = __float2bfloat16(f2), h3 = __float2bfloat16(f3);
                    Ts_hi[sa + nb] = pack_bf16(__bfloat162float(h0), __bfloat162float(h1));
                    Ts_hi[sb + nb] = pack_bf16(__bfloat162float(h2), __bfloat162float(h3));
                    Ts_lo[sa + nb] = pack_bf16(f0 - __bfloat162float(h0), f1 - __bfloat162float(h1));
                    Ts_lo[sb + nb] = pack_bf16(f2 - __bfloat162float(h2), f3 - __bfloat162float(h3));
                }
            }
        }
        __syncthreads();

        // ---- GEMM2: out = T @ W2 + b2 -> gmem  (dual-mb) ----
        #pragma unroll 1
        for (int mb = 0; mb < 8; mb += 2) {
            float acc[2][2][4];
            #pragma unroll
            for (int mi = 0; mi < 2; mi++)
                #pragma unroll
                for (int nb = 0; nb < 2; nb++)
                    #pragma unroll
                    for (int q = 0; q < 4; q++) acc[mi][nb][q] = 0.f;
            int ra0 = (mb * 16 + gid) * ROWSTRIDE;
            int rb0 = ra0 + 8 * ROWSTRIDE;
            int ra1 = ra0 + 16 * ROWSTRIDE;
            int rb1 = ra1 + 8 * ROWSTRIDE;
            #pragma unroll
            for (int ks = 0; ks < 8; ks++) {
                uint2 ah0  = *(const uint2*)(Ts_hi + ra0 + ks * 8 + tg * 2);
                uint2 ahb0 = *(const uint2*)(Ts_hi + rb0 + ks * 8 + tg * 2);
                uint2 al0  = *(const uint2*)(Ts_lo + ra0 + ks * 8 + tg * 2);
                uint2 alb0 = *(const uint2*)(Ts_lo + rb0 + ks * 8 + tg * 2);
                uint2 ah1  = *(const uint2*)(Ts_hi + ra1 + ks * 8 + tg * 2);
                uint2 ahb1 = *(const uint2*)(Ts_hi + rb1 + ks * 8 + tg * 2);
                uint2 al1  = *(const uint2*)(Ts_lo + ra1 + ks * 8 + tg * 2);
                uint2 alb1 = *(const uint2*)(Ts_lo + rb1 + ks * 8 + tg * 2);
                #pragma unroll
                for (int nb = 0; nb < 2; nb++) {
                    uint2 bh = wB[2][nb][ks];
                    uint2 bl = wB[3][nb][ks];
                    MMA_BF16(acc[0][nb], ah0.x, ahb0.x, ah0.y, ahb0.y, bh.x, bh.y);
                    MMA_BF16(acc[1][nb], ah1.x, ahb1.x, ah1.y, ahb1.y, bh.x, bh.y);
                    MMA_BF16(acc[0][nb], al0.x, alb0.x, al0.y, alb0.y, bh.x, bh.y);
                    MMA_BF16(acc[1][nb], al1.x, alb1.x, al1.y, alb1.y, bh.x, bh.y);
                    MMA_BF16(acc[0][nb], ah0.x, ahb0.x, ah0.y, ahb0.y, bl.x, bl.y);
                    MMA_BF16(acc[1][nb], ah1.x, ahb1.x, ah1.y, ahb1.y, bl.x, bl.y);
                }
            }
            #pragma unroll
            for (int mi = 0; mi < 2; mi++) {
                int r0 = row0 + (mb + mi) * 16 + gid;
                int r1 = r0 + 8;
                #pragma unroll
                for (int nb = 0; nb < 2; nb++) {
                    int col = 16 * w + 8 * nb + 2 * tg;
                    if (r0 < n) {
                        float2 o0 = make_float2(acc[mi][nb][0] + b2v[nb].x,
                                                acc[mi][nb][1] + b2v[nb].y);
                        *(float2*)(x_out + (size_t)r0 * H + col) = o0;
                        if (h_out) *(float2*)(h_out + (size_t)r0 * H + col) = o0;
                    }
                    if (r1 < n) {
                        float2 o1 = make_float2(acc[mi][nb][2] + b2v[nb].x,
                                                acc[mi][nb][3] + b2v[nb].y);
                        *(float2*)(x_out + (size_t)r1 * H + col) = o1;
                        if (h_out) *(float2*)(h_out + (size_t)r1 * H + col) = o1;
                    }
                }
            }
        }
        __syncthreads();
    }
}

// batch_vec -> float tail of the output
__global__ void batch_kernel(const int* __restrict__ bv, float* __restrict__ out, int n) {
    int i = blockIdx.x * blockDim.x + threadIdx.x;
    if (i < n) out[i] = (float)bv[i];
}

extern "C" void kernel_launch(void* const* d_in, const int* in_sizes, int n_in,
                              void* d_out, int out_size) {
    const float* emb       = (const float*)d_in[0];
    const float* We        = (const float*)d_in[1];
    const float* be        = (const float*)d_in[2];
    const float* W1        = (const float*)d_in[3];
    const float* b1        = (const float*)d_in[4];
    const float* W2        = (const float*)d_in[5];
    const float* b2        = (const float*)d_in[6];
    const float* edge_attr = (const float*)d_in[7];
    const int*   z         = (const int*)d_in[8];
    const int*   ei        = (const int*)d_in[9];
    const int*   bv        = (const int*)d_in[10];

    int n = in_sizes[8];
    int E = in_sizes[9] / 2;
    float* out = (float*)d_out;

    float *gx, *gh;
    uint32_t* gwf;
    cudaGetSymbolAddress((void**)&gx, g_x);
    cudaGetSymbolAddress((void**)&gh, g_h);
    cudaGetSymbolAddress((void**)&gwf, g_wfrag);

    cudaFuncSetAttribute(mlp_kernel, cudaFuncAttributeMaxDynamicSharedMemorySize,
                         MLP_SMEM);

    wprep_kernel<<<(3 * 8 * 4 * 2 * 8 * 32 * 2 + 255) / 256, 256>>>(W1, W2);
    embed_kernel<<<(n * 32 + 255) / 256, 256>>>(emb, z, gx, gh, n);

    for (int l = 0; l < 3; l++) {
        edge_kernel<<<4096, 256>>>(gx, gh, edge_attr, ei,
                                   We + (size_t)l * 4 * H, be + (size_t)l * H, E);
        bool last = (l == 2);
        mlp_kernel<<<148, MLP_THREADS, MLP_SMEM>>>(
            gh,
            gwf + (size_t)l * 8 * 4 * 2 * 8 * 32 * 2,
            b1 + (size_t)l * H, b2 + (size_t)l * H,
            last ? out : gx,
            last ? nullptr : gh,
            n);
    }

    if (out_size >= n * H + n) {
        batch_kernel<<<(n + 255) / 256, 256>>>(bv, out + (size_t)n * H, n);
    }
}

// round 10
// speedup vs baseline: 1.3215x; 1.0605x over previous
#include <cuda_runtime.h>
#include <cuda_bf16.h>
#include <cstdint>

#define H 128
#define NMAX 100000
#define TM 128
#define MLP_THREADS 512
#define ROWSTRIDE 72                        // u32 per row: 8-bank row skew -> conflict-free LDS.64
#define TILE_U32 (128 * ROWSTRIDE)          // 9216 u32 per hi/lo buffer
#define MLP_SMEM (6 * TILE_U32 * 4)         // Hs(hi,lo) + Ts0(hi,lo) + Ts1(hi,lo) = 221184 B

// Scratch (device globals: no allocation allowed)
__device__ __align__(16) float g_x[(size_t)NMAX * H];
__device__ __align__(16) float g_h[(size_t)NMAX * H];
// weight fragments: [warpslot 8][img 4][nb 2][ks 8][lane 32][2] u32 per layer
__device__ __align__(16) uint32_t g_wfrag[3 * 8 * 4 * 2 * 8 * 32 * 2];

__device__ __forceinline__ uint32_t pack_bf16(float x, float y) {
    __nv_bfloat162 t = __floats2bfloat162_rn(x, y);
    return *(uint32_t*)&t;
}
// permuted pair index: pair j (cols 2j,2j+1) -> slot so that a0/a2 are adjacent
__device__ __forceinline__ int pidx(int j) {
    return ((j >> 3) << 3) + ((j & 3) << 1) + ((j >> 2) & 1);
}
__device__ __forceinline__ float silu_fast(float f) {
    float th;
    asm("tanh.approx.f32 %0, %1;" : "=f"(th) : "f"(0.5f * f));
    return f * fmaf(0.5f, th, 0.5f);
}

#define MMA_BF16(c, A0, A1, A2, A3, B0, B1)                                   \
    asm volatile("mma.sync.aligned.m16n8k16.row.col.f32.bf16.bf16.f32 "       \
                 "{%0,%1,%2,%3}, {%4,%5,%6,%7}, {%8,%9}, {%0,%1,%2,%3};"      \
                 : "+f"(c[0]), "+f"(c[1]), "+f"(c[2]), "+f"(c[3])             \
                 : "r"(A0), "r"(A1), "r"(A2), "r"(A3), "r"(B0), "r"(B1));

// ---------------------------------------------------------------------------
// Weight prep: split W1/W2 (f32 [k][n]) into bf16 hi/lo mma B-fragments,
// laid out exactly in the per-warp register-load order.
// ---------------------------------------------------------------------------
__global__ void wprep_kernel(const float* __restrict__ W1,
                             const float* __restrict__ W2) {
    int idx = blockIdx.x * blockDim.x + threadIdx.x;
    if (idx >= 3 * 8 * 4 * 2 * 8 * 32 * 2) return;
    int r    = idx & 1;
    int lane = (idx >> 1) & 31;
    int ks   = (idx >> 6) & 7;
    int nb   = (idx >> 9) & 1;
    int img  = (idx >> 10) & 3;
    int w    = (idx >> 12) & 7;
    int l    = idx >> 15;
    int gid = lane >> 2, tg = lane & 3;
    int mat = img >> 1, hl = img & 1;
    int n  = w * 16 + nb * 8 + gid;
    int k0 = ks * 16 + tg * 2 + r * 8;
    const float* W = (mat ? W2 : W1) + (size_t)l * H * H;
    float v0 = W[k0 * H + n];
    float v1 = W[(k0 + 1) * H + n];
    __nv_bfloat16 h0 = __float2bfloat16(v0);
    __nv_bfloat16 h1 = __float2bfloat16(v1);
    float o0 = hl ? (v0 - __bfloat162float(h0)) : __bfloat162float(h0);
    float o1 = hl ? (v1 - __bfloat162float(h1)) : __bfloat162float(h1);
    g_wfrag[idx] = pack_bf16(o0, o1);
}

// ---------------------------------------------------------------------------
// Embedding gather: x[i] = emb[z[i]], h[i] = x[i]
// ---------------------------------------------------------------------------
__global__ void embed_kernel(const float* __restrict__ emb,
                             const int* __restrict__ z,
                             float* __restrict__ x, float* __restrict__ h,
                             int n) {
    int i = blockIdx.x * blockDim.x + threadIdx.x;
    if (i >= n * 32) return;
    int node = i >> 5;
    int c = i & 31;
    float4 v = ((const float4*)emb)[(size_t)z[node] * 32 + c];
    ((float4*)x)[i] = v;
    ((float4*)h)[i] = v;
}

// ---------------------------------------------------------------------------
// Edge/message kernel: one warp per 4 edges (pipelined), lane = 4 channels.
// ---------------------------------------------------------------------------
__global__ void edge_kernel(const float* __restrict__ x,
                            float* __restrict__ h,
                            const float* __restrict__ edge_attr,
                            const int* __restrict__ ei,
                            const float* __restrict__ We,
                            const float* __restrict__ be,
                            int E) {
    __shared__ float Wes[4 * H];
    __shared__ float bes[H];
    int tid = threadIdx.x;
    for (int i = tid; i < 4 * H; i += blockDim.x) Wes[i] = We[i];
    for (int i = tid; i < H; i += blockDim.x) bes[i] = be[i];
    __syncthreads();

    int lane = tid & 31;
    int warp = blockIdx.x * (blockDim.x >> 5) + (tid >> 5);
    int nwarps = gridDim.x * (blockDim.x >> 5);

    float4 w0 = ((const float4*)Wes)[0 * 32 + lane];
    float4 w1 = ((const float4*)Wes)[1 * 32 + lane];
    float4 w2 = ((const float4*)Wes)[2 * 32 + lane];
    float4 w3 = ((const float4*)Wes)[3 * 32 + lane];
    float4 bb = ((const float4*)bes)[lane];

    int stride = nwarps * 4;
    #pragma unroll 1
    for (int e0 = warp * 4; e0 < E; e0 += stride) {
        int ne = E - e0; if (ne > 4) ne = 4;
        int s[4], d[4];
        float4 ea[4], xv[4];
        #pragma unroll
        for (int j = 0; j < 4; j++)
            if (j < ne) { s[j] = ei[e0 + j]; d[j] = ei[E + e0 + j]; }
        #pragma unroll
        for (int j = 0; j < 4; j++)
            if (j < ne) ea[j] = ((const float4*)edge_attr)[e0 + j];
        #pragma unroll
        for (int j = 0; j < 4; j++)
            if (j < ne) xv[j] = ((const float4*)x)[(size_t)s[j] * 32 + lane];
        #pragma unroll
        for (int j = 0; j < 4; j++) {
            if (j >= ne) break;
            float m0 = xv[j].x + bb.x + ea[j].x * w0.x + ea[j].y * w1.x + ea[j].z * w2.x + ea[j].w * w3.x;
            float m1 = xv[j].y + bb.y + ea[j].x * w0.y + ea[j].y * w1.y + ea[j].z * w2.y + ea[j].w * w3.y;
            float m2 = xv[j].z + bb.z + ea[j].x * w0.z + ea[j].y * w1.z + ea[j].z * w2.z + ea[j].w * w3.z;
            float m3 = xv[j].w + bb.w + ea[j].x * w0.w + ea[j].y * w1.w + ea[j].z * w2.w + ea[j].w * w3.w;
            m0 = fmaxf(m0, 0.f); m1 = fmaxf(m1, 0.f);
            m2 = fmaxf(m2, 0.f); m3 = fmaxf(m3, 0.f);
            float* dptr = h + (size_t)d[j] * H + lane * 4;
            asm volatile("red.global.add.v4.f32 [%0], {%1,%2,%3,%4};"
                         :: "l"(dptr), "f"(m0), "f"(m1), "f"(m2), "f"(m3)
                         : "memory");
        }
    }
}

// ---------------------------------------------------------------------------
// Warp-specialized fused 2-layer MLP (bf16x3 mma.sync):
//   warps 0-7  (group 0): convert(t) -> GEMM1(t) -> silu -> Ts[buf]
//   warps 8-15 (group 1): GEMM2(t-1) from Ts[buf^1] -> bias -> gmem
// One-tile software pipeline, 4 warps/SMSP, per-group weight regs only.
// ---------------------------------------------------------------------------
__global__ void __launch_bounds__(MLP_THREADS, 1)
mlp_kernel(const float* __restrict__ h_in,
           const uint32_t* __restrict__ wfrag,
           const float* __restrict__ b1, const float* __restrict__ b2,
           float* __restrict__ x_out, float* __restrict__ h_out, int n) {
    extern __shared__ __align__(16) uint32_t sm[];
    uint32_t* Hs_hi = sm;
    uint32_t* Hs_lo = sm + TILE_U32;
    // Ts buffers: sm + (2 + 2*buf)*TILE_U32 (hi), +TILE_U32 (lo)

    int tid = threadIdx.x, w = tid >> 5, lane = tid & 31;
    int group = w >> 3;          // 0 = W1/convert, 1 = W2/store
    int wl = w & 7;              // warp slot within group (16-col slice)
    int gid = lane >> 2, tg = lane & 3;

    // this warp's weight fragments for ITS matrix only (64 regs)
    uint2 wB[2][2][8];           // [hl][nb][ks]
    {
        const uint2* wp = (const uint2*)wfrag + (size_t)wl * 4 * 2 * 8 * 32;
        #pragma unroll
        for (int hl = 0; hl < 2; hl++)
            #pragma unroll
            for (int nb = 0; nb < 2; nb++)
                #pragma unroll
                for (int ks = 0; ks < 8; ks++)
                    wB[hl][nb][ks] =
                        wp[((((group * 2 + hl) * 2) + nb) * 8 + ks) * 32 + lane];
    }
    const float* bsrc = group ? b2 : b1;
    float2 bv[2];
    #pragma unroll
    for (int nb = 0; nb < 2; nb++)
        bv[nb] = *(const float2*)(bsrc + 16 * wl + 8 * nb + 2 * tg);

    int ntiles = (n + TM - 1) / TM;
    int bid = blockIdx.x;
    int ntl = (bid < ntiles) ? ((ntiles - 1 - bid) / gridDim.x + 1) : 0;

    #pragma unroll 1
    for (int it = 0; it <= ntl; it++) {
        int buf = it & 1;
        if (group == 0) {
            if (it < ntl) {
                int row0 = (bid + it * gridDim.x) * TM;
                // ---- convert: gmem -> bf16 hi/lo Hs ----
                #pragma unroll 4
                for (int it2 = 0; it2 < 16; it2++) {
                    int i = tid + it2 * 256;
                    int row = i >> 5;
                    int c4 = i & 31;
                    float4 v = make_float4(0.f, 0.f, 0.f, 0.f);
                    if (row0 + row < n)
                        v = *(const float4*)(h_in + (size_t)(row0 + row) * H + c4 * 4);
                    __nv_bfloat16 hx = __float2bfloat16(v.x), hy = __float2bfloat16(v.y);
                    __nv_bfloat16 hz = __float2bfloat16(v.z), hw = __float2bfloat16(v.w);
                    int base = row * ROWSTRIDE;
                    int p0 = pidx(2 * c4), p1 = pidx(2 * c4 + 1);
                    Hs_hi[base + p0] = pack_bf16(__bfloat162float(hx), __bfloat162float(hy));
                    Hs_hi[base + p1] = pack_bf16(__bfloat162float(hz), __bfloat162float(hw));
                    Hs_lo[base + p0] = pack_bf16(v.x - __bfloat162float(hx), v.y - __bfloat162float(hy));
                    Hs_lo[base + p1] = pack_bf16(v.z - __bfloat162float(hz), v.w - __bfloat162float(hw));
                }
                asm volatile("bar.sync 1, 256;" ::: "memory");

                // ---- GEMM1 + silu -> Ts[buf] ----
                uint32_t* Ts_hi = sm + (2 + 2 * buf) * TILE_U32;
                uint32_t* Ts_lo = Ts_hi + TILE_U32;
                #pragma unroll 1
                for (int mb = 0; mb < 8; mb++) {
                    float acc[2][4] = {{0.f, 0.f, 0.f, 0.f}, {0.f, 0.f, 0.f, 0.f}};
                    int ra = (mb * 16 + gid) * ROWSTRIDE;
                    int rb = ra + 8 * ROWSTRIDE;
                    #pragma unroll
                    for (int ks = 0; ks < 8; ks++) {
                        uint2 ah  = *(const uint2*)(Hs_hi + ra + ks * 8 + tg * 2);
                        uint2 ahb = *(const uint2*)(Hs_hi + rb + ks * 8 + tg * 2);
                        uint2 al  = *(const uint2*)(Hs_lo + ra + ks * 8 + tg * 2);
                        uint2 alb = *(const uint2*)(Hs_lo + rb + ks * 8 + tg * 2);
                        #pragma unroll
                        for (int nb = 0; nb < 2; nb++) {
                            uint2 bh = wB[0][nb][ks];
                            uint2 bl = wB[1][nb][ks];
                            MMA_BF16(acc[nb], ah.x, ahb.x, ah.y, ahb.y, bh.x, bh.y);
                            MMA_BF16(acc[nb], al.x, alb.x, al.y, alb.y, bh.x, bh.y);
                            MMA_BF16(acc[nb], ah.x, ahb.x, ah.y, ahb.y, bl.x, bl.y);
                        }
                    }
                    int sa = (mb * 16 + gid) * ROWSTRIDE + 8 * wl + 2 * tg;
                    int sb = sa + 8 * ROWSTRIDE;
                    #pragma unroll
                    for (int nb = 0; nb < 2; nb++) {
                        float f0 = silu_fast(acc[nb][0] + bv[nb].x);
                        float f1 = silu_fast(acc[nb][1] + bv[nb].y);
                        float f2 = silu_fast(acc[nb][2] + bv[nb].x);
                        float f3 = silu_fast(acc[nb][3] + bv[nb].y);
                        __nv_bfloat16 h0 = __float2bfloat16(f0), h1 = __float2bfloat16(f1);
                        __nv_bfloat16 h2 = __float2bfloat16(f2), h3 = __float2bfloat16(f3);
                        Ts_hi[sa + nb] = pack_bf16(__bfloat162float(h0), __bfloat162float(h1));
                        Ts_hi[sb + nb] = pack_bf16(__bfloat162float(h2), __bfloat162float(h3));
                        Ts_lo[sa + nb] = pack_bf16(f0 - __bfloat162float(h0), f1 - __bfloat162float(h1));
                        Ts_lo[sb + nb] = pack_bf16(f2 - __bfloat162float(h2), f3 - __bfloat162float(h3));
                    }
                }
            }
        } else {
            if (it > 0) {
                int row0 = (bid + (it - 1) * gridDim.x) * TM;
                uint32_t* Ts_hi = sm + (2 + 2 * (buf ^ 1)) * TILE_U32;
                uint32_t* Ts_lo = Ts_hi + TILE_U32;
                #pragma unroll 1
                for (int mb = 0; mb < 8; mb++) {
                    float acc[2][4] = {{0.f, 0.f, 0.f, 0.f}, {0.f, 0.f, 0.f, 0.f}};
                    int ra = (mb * 16 + gid) * ROWSTRIDE;
                    int rb = ra + 8 * ROWSTRIDE;
                    #pragma unroll
                    for (int ks = 0; ks < 8; ks++) {
                        uint2 ah  = *(const uint2*)(Ts_hi + ra + ks * 8 + tg * 2);
                        uint2 ahb = *(const uint2*)(Ts_hi + rb + ks * 8 + tg * 2);
                        uint2 al  = *(const uint2*)(Ts_lo + ra + ks * 8 + tg * 2);
                        uint2 alb = *(const uint2*)(Ts_lo + rb + ks * 8 + tg * 2);
                        #pragma unroll
                        for (int nb = 0; nb < 2; nb++) {
                            uint2 bh = wB[0][nb][ks];
                            uint2 bl = wB[1][nb][ks];
                            MMA_BF16(acc[nb], ah.x, ahb.x, ah.y, ahb.y, bh.x, bh.y);
                            MMA_BF16(acc[nb], al.x, alb.x, al.y, alb.y, bh.x, bh.y);
                            MMA_BF16(acc[nb], ah.x, ahb.x, ah.y, ahb.y, bl.x, bl.y);
                        }
                    }
                    int r0 = row0 + mb * 16 + gid;
                    int r1 = r0 + 8;
                    #pragma unroll
                    for (int nb = 0; nb < 2; nb++) {
                        int col = 16 * wl + 8 * nb + 2 * tg;
                        if (r0 < n) {
                            float2 o0 = make_float2(acc[nb][0] + bv[nb].x,
                                                    acc[nb][1] + bv[nb].y);
                            *(float2*)(x_out + (size_t)r0 * H + col) = o0;
                            if (h_out) *(float2*)(h_out + (size_t)r0 * H + col) = o0;
                        }
                        if (r1 < n) {
                            float2 o1 = make_float2(acc[nb][2] + bv[nb].x,
                                                    acc[nb][3] + bv[nb].y);
                            *(float2*)(x_out + (size_t)r1 * H + col) = o1;
                            if (h_out) *(float2*)(h_out + (size_t)r1 * H + col) = o1;
                        }
                    }
                }
            }
        }
        __syncthreads();
    }
}

// batch_vec -> float tail of the output
__global__ void batch_kernel(const int* __restrict__ bv, float* __restrict__ out, int n) {
    int i = blockIdx.x * blockDim.x + threadIdx.x;
    if (i < n) out[i] = (float)bv[i];
}

extern "C" void kernel_launch(void* const* d_in, const int* in_sizes, int n_in,
                              void* d_out, int out_size) {
    const float* emb       = (const float*)d_in[0];
    const float* We        = (const float*)d_in[1];
    const float* be        = (const float*)d_in[2];
    const float* W1        = (const float*)d_in[3];
    const float* b1        = (const float*)d_in[4];
    const float* W2        = (const float*)d_in[5];
    const float* b2        = (const float*)d_in[6];
    const float* edge_attr = (const float*)d_in[7];
    const int*   z         = (const int*)d_in[8];
    const int*   ei        = (const int*)d_in[9];
    const int*   bv        = (const int*)d_in[10];

    int n = in_sizes[8];
    int E = in_sizes[9] / 2;
    float* out = (float*)d_out;

    float *gx, *gh;
    uint32_t* gwf;
    cudaGetSymbolAddress((void**)&gx, g_x);
    cudaGetSymbolAddress((void**)&gh, g_h);
    cudaGetSymbolAddress((void**)&gwf, g_wfrag);

    cudaFuncSetAttribute(mlp_kernel, cudaFuncAttributeMaxDynamicSharedMemorySize,
                         MLP_SMEM);

    wprep_kernel<<<(3 * 8 * 4 * 2 * 8 * 32 * 2 + 255) / 256, 256>>>(W1, W2);
    embed_kernel<<<(n * 32 + 255) / 256, 256>>>(emb, z, gx, gh, n);

    for (int l = 0; l < 3; l++) {
        edge_kernel<<<4096, 256>>>(gx, gh, edge_attr, ei,
                                   We + (size_t)l * 4 * H, be + (size_t)l * H, E);
        bool last = (l == 2);
        mlp_kernel<<<148, MLP_THREADS, MLP_SMEM>>>(
            gh,
            gwf + (size_t)l * 8 * 4 * 2 * 8 * 32 * 2,
            b1 + (size_t)l * H, b2 + (size_t)l * H,
            last ? out : gx,
            last ? nullptr : gh,
            n);
    }

    if (out_size >= n * H + n) {
        batch_kernel<<<(n + 255) / 256, 256>>>(bv, out + (size_t)n * H, n);
    }
}

// round 11
// speedup vs baseline: 1.3309x; 1.0071x over previous
#include <cuda_runtime.h>
#include <cuda_bf16.h>
#include <cstdint>

#define H 128
#define NMAX 100000
#define TM 128
#define MLP_THREADS 512
#define ROWSTRIDE 72                        // u32 per row: 8-bank row skew -> conflict-free LDS.64
#define TILE_U32 (128 * ROWSTRIDE)          // 9216 u32 per hi/lo buffer
#define MLP_SMEM (6 * TILE_U32 * 4)         // Hs(hi,lo) + Ts0(hi,lo) + Ts1(hi,lo) = 221184 B
#define WPREP_TOTAL (3 * 8 * 4 * 2 * 8 * 32 * 2)

// Scratch (device globals: no allocation allowed)
__device__ __align__(16) float g_x[(size_t)NMAX * H];
__device__ __align__(16) float g_h[(size_t)NMAX * H];
// weight fragments: [layer][warpslot 8][img 4][nb 2][ks 8][lane 32][2] u32
__device__ __align__(16) uint32_t g_wfrag[WPREP_TOTAL];

__device__ __forceinline__ uint32_t pack_bf16(float x, float y) {
    __nv_bfloat162 t = __floats2bfloat162_rn(x, y);
    return *(uint32_t*)&t;
}
// permuted pair index: pair j (cols 2j,2j+1) -> slot so that a0/a2 are adjacent
__device__ __forceinline__ int pidx(int j) {
    return ((j >> 3) << 3) + ((j & 3) << 1) + ((j >> 2) & 1);
}
__device__ __forceinline__ float silu_fast(float f) {
    float th;
    asm("tanh.approx.f32 %0, %1;" : "=f"(th) : "f"(0.5f * f));
    return f * fmaf(0.5f, th, 0.5f);
}

#define MMA_BF16(c, A0, A1, A2, A3, B0, B1)                                   \
    asm volatile("mma.sync.aligned.m16n8k16.row.col.f32.bf16.bf16.f32 "       \
                 "{%0,%1,%2,%3}, {%4,%5,%6,%7}, {%8,%9}, {%0,%1,%2,%3};"      \
                 : "+f"(c[0]), "+f"(c[1]), "+f"(c[2]), "+f"(c[3])             \
                 : "r"(A0), "r"(A1), "r"(A2), "r"(A3), "r"(B0), "r"(B1));

// ---------------------------------------------------------------------------
// Fused prep: blocks [0, nembed) do the embedding gather (x, h init);
// blocks [nembed, nembed + 384) split W1/W2 into bf16 hi/lo mma B-fragments.
// ---------------------------------------------------------------------------
__global__ void prep_kernel(const float* __restrict__ emb,
                            const int* __restrict__ z,
                            float* __restrict__ x, float* __restrict__ h,
                            int n, int nembed,
                            const float* __restrict__ W1,
                            const float* __restrict__ W2) {
    int b = blockIdx.x;
    if (b < nembed) {
        int i = b * 256 + threadIdx.x;
        if (i >= n * 32) return;
        int node = i >> 5;
        int c = i & 31;
        float4 v = ((const float4*)emb)[(size_t)z[node] * 32 + c];
        ((float4*)x)[i] = v;
        ((float4*)h)[i] = v;
    } else {
        int idx = (b - nembed) * 256 + threadIdx.x;
        if (idx >= WPREP_TOTAL) return;
        int r    = idx & 1;
        int lane = (idx >> 1) & 31;
        int ks   = (idx >> 6) & 7;
        int nb   = (idx >> 9) & 1;
        int img  = (idx >> 10) & 3;
        int w    = (idx >> 12) & 7;
        int l    = idx >> 15;
        int gid = lane >> 2, tg = lane & 3;
        int mat = img >> 1, hl = img & 1;
        int nn = w * 16 + nb * 8 + gid;
        int k0 = ks * 16 + tg * 2 + r * 8;
        const float* W = (mat ? W2 : W1) + (size_t)l * H * H;
        float v0 = W[k0 * H + nn];
        float v1 = W[(k0 + 1) * H + nn];
        __nv_bfloat16 h0 = __float2bfloat16(v0);
        __nv_bfloat16 h1 = __float2bfloat16(v1);
        float o0 = hl ? (v0 - __bfloat162float(h0)) : __bfloat162float(h0);
        float o1 = hl ? (v1 - __bfloat162float(h1)) : __bfloat162float(h1);
        g_wfrag[idx] = pack_bf16(o0, o1);
    }
}

// ---------------------------------------------------------------------------
// Edge/message kernel: one warp per 4 edges (pipelined), lane = 4 channels.
// ---------------------------------------------------------------------------
__global__ void edge_kernel(const float* __restrict__ x,
                            float* __restrict__ h,
                            const float* __restrict__ edge_attr,
                            const int* __restrict__ ei,
                            const float* __restrict__ We,
                            const float* __restrict__ be,
                            int E) {
    __shared__ float Wes[4 * H];
    __shared__ float bes[H];
    int tid = threadIdx.x;
    for (int i = tid; i < 4 * H; i += blockDim.x) Wes[i] = We[i];
    for (int i = tid; i < H; i += blockDim.x) bes[i] = be[i];
    __syncthreads();

    int lane = tid & 31;
    int warp = blockIdx.x * (blockDim.x >> 5) + (tid >> 5);
    int nwarps = gridDim.x * (blockDim.x >> 5);

    float4 w0 = ((const float4*)Wes)[0 * 32 + lane];
    float4 w1 = ((const float4*)Wes)[1 * 32 + lane];
    float4 w2 = ((const float4*)Wes)[2 * 32 + lane];
    float4 w3 = ((const float4*)Wes)[3 * 32 + lane];
    float4 bb = ((const float4*)bes)[lane];

    int stride = nwarps * 4;
    #pragma unroll 1
    for (int e0 = warp * 4; e0 < E; e0 += stride) {
        int ne = E - e0; if (ne > 4) ne = 4;
        int s[4], d[4];
        float4 ea[4], xv[4];
        #pragma unroll
        for (int j = 0; j < 4; j++)
            if (j < ne) { s[j] = ei[e0 + j]; d[j] = ei[E + e0 + j]; }
        #pragma unroll
        for (int j = 0; j < 4; j++)
            if (j < ne) ea[j] = ((const float4*)edge_attr)[e0 + j];
        #pragma unroll
        for (int j = 0; j < 4; j++)
            if (j < ne) xv[j] = ((const float4*)x)[(size_t)s[j] * 32 + lane];
        #pragma unroll
        for (int j = 0; j < 4; j++) {
            if (j >= ne) break;
            float m0 = xv[j].x + bb.x + ea[j].x * w0.x + ea[j].y * w1.x + ea[j].z * w2.x + ea[j].w * w3.x;
            float m1 = xv[j].y + bb.y + ea[j].x * w0.y + ea[j].y * w1.y + ea[j].z * w2.y + ea[j].w * w3.y;
            float m2 = xv[j].z + bb.z + ea[j].x * w0.z + ea[j].y * w1.z + ea[j].z * w2.z + ea[j].w * w3.z;
            float m3 = xv[j].w + bb.w + ea[j].x * w0.w + ea[j].y * w1.w + ea[j].z * w2.w + ea[j].w * w3.w;
            m0 = fmaxf(m0, 0.f); m1 = fmaxf(m1, 0.f);
            m2 = fmaxf(m2, 0.f); m3 = fmaxf(m3, 0.f);
            float* dptr = h + (size_t)d[j] * H + lane * 4;
            asm volatile("red.global.add.v4.f32 [%0], {%1,%2,%3,%4};"
                         :: "l"(dptr), "f"(m0), "f"(m1), "f"(m2), "f"(m3)
                         : "memory");
        }
    }
}

// ---------------------------------------------------------------------------
// Warp-specialized fused 2-layer MLP (bf16x3 mma.sync):
//   convert(t): split across BOTH groups at iteration top (rows 0-63 / 64-127)
//   warps 0-7  (group 0): GEMM1(t) -> silu -> Ts[buf]
//   warps 8-15 (group 1): GEMM2(t-1) from Ts[buf^1] -> bias -> gmem
// One-tile software pipeline, 4 warps/SMSP, per-group weight regs only.
// ---------------------------------------------------------------------------
__global__ void __launch_bounds__(MLP_THREADS, 1)
mlp_kernel(const float* __restrict__ h_in,
           const uint32_t* __restrict__ wfrag,
           const float* __restrict__ b1, const float* __restrict__ b2,
           float* __restrict__ x_out, float* __restrict__ h_out, int n) {
    extern __shared__ __align__(16) uint32_t sm[];
    uint32_t* Hs_hi = sm;
    uint32_t* Hs_lo = sm + TILE_U32;
    // Ts buffers: sm + (2 + 2*buf)*TILE_U32 (hi), +TILE_U32 (lo)

    int tid = threadIdx.x, w = tid >> 5, lane = tid & 31;
    int group = w >> 3;          // 0 = W1 group, 1 = W2/store group
    int wl = w & 7;              // warp slot within group (16-col slice)
    int gt = tid & 255;          // thread index within group
    int gid = lane >> 2, tg = lane & 3;

    // this warp's weight fragments for ITS matrix only (64 regs)
    uint2 wB[2][2][8];           // [hl][nb][ks]
    {
        const uint2* wp = (const uint2*)wfrag + (size_t)wl * 4 * 2 * 8 * 32;
        #pragma unroll
        for (int hl = 0; hl < 2; hl++)
            #pragma unroll
            for (int nb = 0; nb < 2; nb++)
                #pragma unroll
                for (int ks = 0; ks < 8; ks++)
                    wB[hl][nb][ks] =
                        wp[((((group * 2 + hl) * 2) + nb) * 8 + ks) * 32 + lane];
    }
    const float* bsrc = group ? b2 : b1;
    float2 bv[2];
    #pragma unroll
    for (int nb = 0; nb < 2; nb++)
        bv[nb] = *(const float2*)(bsrc + 16 * wl + 8 * nb + 2 * tg);

    int ntiles = (n + TM - 1) / TM;
    int bid = blockIdx.x;
    int ntl = (bid < ntiles) ? ((ntiles - 1 - bid) / gridDim.x + 1) : 0;

    #pragma unroll 1
    for (int it = 0; it <= ntl; it++) {
        int buf = it & 1;

        // ---- convert tile t=it (both groups, half each) ----
        if (it < ntl) {
            int row0 = (bid + it * gridDim.x) * TM;
            #pragma unroll 4
            for (int it2 = 0; it2 < 8; it2++) {
                int i = gt + (group * 8 + it2) * 256;
                int row = i >> 5;
                int c4 = i & 31;
                float4 v = make_float4(0.f, 0.f, 0.f, 0.f);
                if (row0 + row < n)
                    v = *(const float4*)(h_in + (size_t)(row0 + row) * H + c4 * 4);
                __nv_bfloat16 hx = __float2bfloat16(v.x), hy = __float2bfloat16(v.y);
                __nv_bfloat16 hz = __float2bfloat16(v.z), hw = __float2bfloat16(v.w);
                int base = row * ROWSTRIDE;
                int p0 = pidx(2 * c4), p1 = pidx(2 * c4 + 1);
                Hs_hi[base + p0] = pack_bf16(__bfloat162float(hx), __bfloat162float(hy));
                Hs_hi[base + p1] = pack_bf16(__bfloat162float(hz), __bfloat162float(hw));
                Hs_lo[base + p0] = pack_bf16(v.x - __bfloat162float(hx), v.y - __bfloat162float(hy));
                Hs_lo[base + p1] = pack_bf16(v.z - __bfloat162float(hz), v.w - __bfloat162float(hw));
            }
        }
        __syncthreads();

        if (group == 0) {
            if (it < ntl) {
                // ---- GEMM1 + silu -> Ts[buf] ----
                uint32_t* Ts_hi = sm + (2 + 2 * buf) * TILE_U32;
                uint32_t* Ts_lo = Ts_hi + TILE_U32;
                #pragma unroll 1
                for (int mb = 0; mb < 8; mb++) {
                    float acc[2][4] = {{0.f, 0.f, 0.f, 0.f}, {0.f, 0.f, 0.f, 0.f}};
                    int ra = (mb * 16 + gid) * ROWSTRIDE;
                    int rb = ra + 8 * ROWSTRIDE;
                    #pragma unroll
                    for (int ks = 0; ks < 8; ks++) {
                        uint2 ah  = *(const uint2*)(Hs_hi + ra + ks * 8 + tg * 2);
                        uint2 ahb = *(const uint2*)(Hs_hi + rb + ks * 8 + tg * 2);
                        uint2 al  = *(const uint2*)(Hs_lo + ra + ks * 8 + tg * 2);
                        uint2 alb = *(const uint2*)(Hs_lo + rb + ks * 8 + tg * 2);
                        #pragma unroll
                        for (int nb = 0; nb < 2; nb++) {
                            uint2 bh = wB[0][nb][ks];
                            uint2 bl = wB[1][nb][ks];
                            MMA_BF16(acc[nb], ah.x, ahb.x, ah.y, ahb.y, bh.x, bh.y);
                            MMA_BF16(acc[nb], al.x, alb.x, al.y, alb.y, bh.x, bh.y);
                            MMA_BF16(acc[nb], ah.x, ahb.x, ah.y, ahb.y, bl.x, bl.y);
                        }
                    }
                    int sa = (mb * 16 + gid) * ROWSTRIDE + 8 * wl + 2 * tg;
                    int sb = sa + 8 * ROWSTRIDE;
                    #pragma unroll
                    for (int nb = 0; nb < 2; nb++) {
                        float f0 = silu_fast(acc[nb][0] + bv[nb].x);
                        float f1 = silu_fast(acc[nb][1] + bv[nb].y);
                        float f2 = silu_fast(acc[nb][2] + bv[nb].x);
                        float f3 = silu_fast(acc[nb][3] + bv[nb].y);
                        __nv_bfloat16 h0 = __float2bfloat16(f0), h1 = __float2bfloat16(f1);
                        __nv_bfloat16 h2 = __float2bfloat16(f2), h3 = __float2bfloat16(f3);
                        Ts_hi[sa + nb] = pack_bf16(__bfloat162float(h0), __bfloat162float(h1));
                        Ts_hi[sb + nb] = pack_bf16(__bfloat162float(h2), __bfloat162float(h3));
                        Ts_lo[sa + nb] = pack_bf16(f0 - __bfloat162float(h0), f1 - __bfloat162float(h1));
                        Ts_lo[sb + nb] = pack_bf16(f2 - __bfloat162float(h2), f3 - __bfloat162float(h3));
                    }
                }
            }
        } else {
            if (it > 0) {
                int row0 = (bid + (it - 1) * gridDim.x) * TM;
                uint32_t* Ts_hi = sm + (2 + 2 * (buf ^ 1)) * TILE_U32;
                uint32_t* Ts_lo = Ts_hi + TILE_U32;
                #pragma unroll 1
                for (int mb = 0; mb < 8; mb++) {
                    float acc[2][4] = {{0.f, 0.f, 0.f, 0.f}, {0.f, 0.f, 0.f, 0.f}};
                    int ra = (mb * 16 + gid) * ROWSTRIDE;
                    int rb = ra + 8 * ROWSTRIDE;
                    #pragma unroll
                    for (int ks = 0; ks < 8; ks++) {
                        uint2 ah  = *(const uint2*)(Ts_hi + ra + ks * 8 + tg * 2);
                        uint2 ahb = *(const uint2*)(Ts_hi + rb + ks * 8 + tg * 2);
                        uint2 al  = *(const uint2*)(Ts_lo + ra + ks * 8 + tg * 2);
                        uint2 alb = *(const uint2*)(Ts_lo + rb + ks * 8 + tg * 2);
                        #pragma unroll
                        for (int nb = 0; nb < 2; nb++) {
                            uint2 bh = wB[0][nb][ks];
                            uint2 bl = wB[1][nb][ks];
                            MMA_BF16(acc[nb], ah.x, ahb.x, ah.y, ahb.y, bh.x, bh.y);
                            MMA_BF16(acc[nb], al.x, alb.x, al.y, alb.y, bh.x, bh.y);
                            MMA_BF16(acc[nb], ah.x, ahb.x, ah.y, ahb.y, bl.x, bl.y);
                        }
                    }
                    int r0 = row0 + mb * 16 + gid;
                    int r1 = r0 + 8;
                    #pragma unroll
                    for (int nb = 0; nb < 2; nb++) {
                        int col = 16 * wl + 8 * nb + 2 * tg;
                        if (r0 < n) {
                            float2 o0 = make_float2(acc[nb][0] + bv[nb].x,
                                                    acc[nb][1] + bv[nb].y);
                            *(float2*)(x_out + (size_t)r0 * H + col) = o0;
                            if (h_out) *(float2*)(h_out + (size_t)r0 * H + col) = o0;
                        }
                        if (r1 < n) {
                            float2 o1 = make_float2(acc[nb][2] + bv[nb].x,
                                                    acc[nb][3] + bv[nb].y);
                            *(float2*)(x_out + (size_t)r1 * H + col) = o1;
                            if (h_out) *(float2*)(h_out + (size_t)r1 * H + col) = o1;
                        }
                    }
                }
            }
        }
        __syncthreads();
    }
}

// batch_vec -> float tail of the output
__global__ void batch_kernel(const int* __restrict__ bv, float* __restrict__ out, int n) {
    int i = blockIdx.x * blockDim.x + threadIdx.x;
    if (i < n) out[i] = (float)bv[i];
}

extern "C" void kernel_launch(void* const* d_in, const int* in_sizes, int n_in,
                              void* d_out, int out_size) {
    const float* emb       = (const float*)d_in[0];
    const float* We        = (const float*)d_in[1];
    const float* be        = (const float*)d_in[2];
    const float* W1        = (const float*)d_in[3];
    const float* b1        = (const float*)d_in[4];
    const float* W2        = (const float*)d_in[5];
    const float* b2        = (const float*)d_in[6];
    const float* edge_attr = (const float*)d_in[7];
    const int*   z         = (const int*)d_in[8];
    const int*   ei        = (const int*)d_in[9];
    const int*   bv        = (const int*)d_in[10];

    int n = in_sizes[8];
    int E = in_sizes[9] / 2;
    float* out = (float*)d_out;

    float *gx, *gh;
    uint32_t* gwf;
    cudaGetSymbolAddress((void**)&gx, g_x);
    cudaGetSymbolAddress((void**)&gh, g_h);
    cudaGetSymbolAddress((void**)&gwf, g_wfrag);

    cudaFuncSetAttribute(mlp_kernel, cudaFuncAttributeMaxDynamicSharedMemorySize,
                         MLP_SMEM);

    int nembed = (n * 32 + 255) / 256;
    int nwprep = (WPREP_TOTAL + 255) / 256;
    prep_kernel<<<nembed + nwprep, 256>>>(emb, z, gx, gh, n, nembed, W1, W2);

    for (int l = 0; l < 3; l++) {
        edge_kernel<<<4096, 256>>>(gx, gh, edge_attr, ei,
                                   We + (size_t)l * 4 * H, be + (size_t)l * H, E);
        bool last = (l == 2);
        mlp_kernel<<<148, MLP_THREADS, MLP_SMEM>>>(
            gh,
            gwf + (size_t)l * 8 * 4 * 2 * 8 * 32 * 2,
            b1 + (size_t)l * H, b2 + (size_t)l * H,
            last ? out : gx,
            last ? nullptr : gh,
            n);
    }

    if (out_size >= n * H + n) {
        batch_kernel<<<(n + 255) / 256, 256>>>(bv, out + (size_t)n * H, n);
    }
}

// round 12
// speedup vs baseline: 1.3354x; 1.0034x over previous
#include <cuda_runtime.h>
#include <cuda_bf16.h>
#include <cstdint>

#define H 128
#define NMAX 100000
#define TM 128
#define MLP_THREADS 512
#define ROWSTRIDE 72                        // u32 per row: 8-bank row skew -> conflict-free LDS.64
#define TILE_U32 (128 * ROWSTRIDE)          // 9216 u32 per hi/lo buffer
#define MLP_SMEM (6 * TILE_U32 * 4)         // Hs(hi,lo) + Ts0(hi,lo) + Ts1(hi,lo) = 221184 B
#define WPREP_TOTAL (3 * 8 * 4 * 2 * 8 * 32 * 2)

// Scratch (device globals: no allocation allowed)
__device__ __align__(16) float g_x[(size_t)NMAX * H];
__device__ __align__(16) float g_h[(size_t)NMAX * H];
// weight fragments: [layer][warpslot 8][img 4][nb 2][ks 8][lane 32][2] u32
__device__ __align__(16) uint32_t g_wfrag[WPREP_TOTAL];

__device__ __forceinline__ uint32_t pack_bf16(float x, float y) {
    __nv_bfloat162 t = __floats2bfloat162_rn(x, y);
    return *(uint32_t*)&t;
}
// permuted pair index: pair j (cols 2j,2j+1) -> slot so that a0/a2 are adjacent
__device__ __forceinline__ int pidx(int j) {
    return ((j >> 3) << 3) + ((j & 3) << 1) + ((j >> 2) & 1);
}
__device__ __forceinline__ float silu_fast(float f) {
    float th;
    asm("tanh.approx.f32 %0, %1;" : "=f"(th) : "f"(0.5f * f));
    return f * fmaf(0.5f, th, 0.5f);
}

#define MMA_BF16(c, A0, A1, A2, A3, B0, B1)                                   \
    asm volatile("mma.sync.aligned.m16n8k16.row.col.f32.bf16.bf16.f32 "       \
                 "{%0,%1,%2,%3}, {%4,%5,%6,%7}, {%8,%9}, {%0,%1,%2,%3};"      \
                 : "+f"(c[0]), "+f"(c[1]), "+f"(c[2]), "+f"(c[3])             \
                 : "r"(A0), "r"(A1), "r"(A2), "r"(A3), "r"(B0), "r"(B1));

// ---------------------------------------------------------------------------
// Fused prep: blocks [0, nembed) do the embedding gather (x, h init);
// blocks [nembed, nembed + 384) split W1/W2 into bf16 hi/lo mma B-fragments.
// ---------------------------------------------------------------------------
__global__ void prep_kernel(const float* __restrict__ emb,
                            const int* __restrict__ z,
                            float* __restrict__ x, float* __restrict__ h,
                            int n, int nembed,
                            const float* __restrict__ W1,
                            const float* __restrict__ W2) {
    int b = blockIdx.x;
    if (b < nembed) {
        int i = b * 256 + threadIdx.x;
        if (i >= n * 32) return;
        int node = i >> 5;
        int c = i & 31;
        float4 v = ((const float4*)emb)[(size_t)z[node] * 32 + c];
        ((float4*)x)[i] = v;
        ((float4*)h)[i] = v;
    } else {
        int idx = (b - nembed) * 256 + threadIdx.x;
        if (idx >= WPREP_TOTAL) return;
        int r    = idx & 1;
        int lane = (idx >> 1) & 31;
        int ks   = (idx >> 6) & 7;
        int nb   = (idx >> 9) & 1;
        int img  = (idx >> 10) & 3;
        int w    = (idx >> 12) & 7;
        int l    = idx >> 15;
        int gid = lane >> 2, tg = lane & 3;
        int mat = img >> 1, hl = img & 1;
        int nn = w * 16 + nb * 8 + gid;
        int k0 = ks * 16 + tg * 2 + r * 8;
        const float* W = (mat ? W2 : W1) + (size_t)l * H * H;
        float v0 = W[k0 * H + nn];
        float v1 = W[(k0 + 1) * H + nn];
        __nv_bfloat16 h0 = __float2bfloat16(v0);
        __nv_bfloat16 h1 = __float2bfloat16(v1);
        float o0 = hl ? (v0 - __bfloat162float(h0)) : __bfloat162float(h0);
        float o1 = hl ? (v1 - __bfloat162float(h1)) : __bfloat162float(h1);
        g_wfrag[idx] = pack_bf16(o0, o1);
    }
}

// ---------------------------------------------------------------------------
// Edge/message kernel: one warp per 4 edges, int4 index loads,
// forced 4 CTAs/SM for latency coverage.
// ---------------------------------------------------------------------------
__global__ void __launch_bounds__(256, 4)
edge_kernel(const float* __restrict__ x,
            float* __restrict__ h,
            const float* __restrict__ edge_attr,
            const int* __restrict__ ei,
            const float* __restrict__ We,
            const float* __restrict__ be,
            int E) {
    __shared__ float Wes[4 * H];
    __shared__ float bes[H];
    int tid = threadIdx.x;
    for (int i = tid; i < 4 * H; i += blockDim.x) Wes[i] = We[i];
    for (int i = tid; i < H; i += blockDim.x) bes[i] = be[i];
    __syncthreads();

    int lane = tid & 31;
    int warp = blockIdx.x * (blockDim.x >> 5) + (tid >> 5);
    int nwarps = gridDim.x * (blockDim.x >> 5);

    float4 w0 = ((const float4*)Wes)[0 * 32 + lane];
    float4 w1 = ((const float4*)Wes)[1 * 32 + lane];
    float4 w2 = ((const float4*)Wes)[2 * 32 + lane];
    float4 w3 = ((const float4*)Wes)[3 * 32 + lane];
    float4 bb = ((const float4*)bes)[lane];

    int E4 = E & ~3;                 // E is a multiple of 4 in practice; guard anyway
    int stride = nwarps * 4;
    #pragma unroll 1
    for (int e0 = warp * 4; e0 < E4; e0 += stride) {
        int4 sv = *(const int4*)(ei + e0);       // 4 src indices
        int4 dv = *(const int4*)(ei + E + e0);   // 4 dst indices
        int s[4] = { sv.x, sv.y, sv.z, sv.w };
        int d[4] = { dv.x, dv.y, dv.z, dv.w };
        float4 ea[4], xv[4];
        #pragma unroll
        for (int j = 0; j < 4; j++) ea[j] = ((const float4*)edge_attr)[e0 + j];
        #pragma unroll
        for (int j = 0; j < 4; j++) xv[j] = ((const float4*)x)[(size_t)s[j] * 32 + lane];
        #pragma unroll
        for (int j = 0; j < 4; j++) {
            float m0 = xv[j].x + bb.x + ea[j].x * w0.x + ea[j].y * w1.x + ea[j].z * w2.x + ea[j].w * w3.x;
            float m1 = xv[j].y + bb.y + ea[j].x * w0.y + ea[j].y * w1.y + ea[j].z * w2.y + ea[j].w * w3.y;
            float m2 = xv[j].z + bb.z + ea[j].x * w0.z + ea[j].y * w1.z + ea[j].z * w2.z + ea[j].w * w3.z;
            float m3 = xv[j].w + bb.w + ea[j].x * w0.w + ea[j].y * w1.w + ea[j].z * w2.w + ea[j].w * w3.w;
            m0 = fmaxf(m0, 0.f); m1 = fmaxf(m1, 0.f);
            m2 = fmaxf(m2, 0.f); m3 = fmaxf(m3, 0.f);
            float* dptr = h + (size_t)d[j] * H + lane * 4;
            asm volatile("red.global.add.v4.f32 [%0], {%1,%2,%3,%4};"
                         :: "l"(dptr), "f"(m0), "f"(m1), "f"(m2), "f"(m3)
                         : "memory");
        }
    }
    // tail (E not multiple of 4)
    if (warp == 0) {
        for (int e = E4 + (tid >> 5); e < E; e += 8) {
            int src = ei[e], dst = ei[E + e];
            float4 eav = ((const float4*)edge_attr)[e];
            float4 xvv = ((const float4*)x)[(size_t)src * 32 + lane];
            float m0 = xvv.x + bb.x + eav.x * w0.x + eav.y * w1.x + eav.z * w2.x + eav.w * w3.x;
            float m1 = xvv.y + bb.y + eav.x * w0.y + eav.y * w1.y + eav.z * w2.y + eav.w * w3.y;
            float m2 = xvv.z + bb.z + eav.x * w0.z + eav.y * w1.z + eav.z * w2.z + eav.w * w3.z;
            float m3 = xvv.w + bb.w + eav.x * w0.w + eav.y * w1.w + eav.z * w2.w + eav.w * w3.w;
            m0 = fmaxf(m0, 0.f); m1 = fmaxf(m1, 0.f);
            m2 = fmaxf(m2, 0.f); m3 = fmaxf(m3, 0.f);
            float* dptr = h + (size_t)dst * H + lane * 4;
            asm volatile("red.global.add.v4.f32 [%0], {%1,%2,%3,%4};"
                         :: "l"(dptr), "f"(m0), "f"(m1), "f"(m2), "f"(m3)
                         : "memory");
        }
    }
}

// ---------------------------------------------------------------------------
// Warp-specialized fused 2-layer MLP (bf16x3 mma.sync):
//   convert(t): split across BOTH groups at iteration top (rows 0-63 / 64-127)
//   warps 0-7  (group 0): GEMM1(t) -> silu -> Ts[buf]
//   warps 8-15 (group 1): GEMM2(t-1) from Ts[buf^1] -> bias -> gmem
// ---------------------------------------------------------------------------
__global__ void __launch_bounds__(MLP_THREADS, 1)
mlp_kernel(const float* __restrict__ h_in,
           const uint32_t* __restrict__ wfrag,
           const float* __restrict__ b1, const float* __restrict__ b2,
           float* __restrict__ x_out, float* __restrict__ h_out, int n) {
    extern __shared__ __align__(16) uint32_t sm[];
    uint32_t* Hs_hi = sm;
    uint32_t* Hs_lo = sm + TILE_U32;
    // Ts buffers: sm + (2 + 2*buf)*TILE_U32 (hi), +TILE_U32 (lo)

    int tid = threadIdx.x, w = tid >> 5, lane = tid & 31;
    int group = w >> 3;          // 0 = W1 group, 1 = W2/store group
    int wl = w & 7;              // warp slot within group (16-col slice)
    int gt = tid & 255;          // thread index within group
    int gid = lane >> 2, tg = lane & 3;

    // this warp's weight fragments for ITS matrix only (64 regs)
    uint2 wB[2][2][8];           // [hl][nb][ks]
    {
        const uint2* wp = (const uint2*)wfrag + (size_t)wl * 4 * 2 * 8 * 32;
        #pragma unroll
        for (int hl = 0; hl < 2; hl++)
            #pragma unroll
            for (int nb = 0; nb < 2; nb++)
                #pragma unroll
                for (int ks = 0; ks < 8; ks++)
                    wB[hl][nb][ks] =
                        wp[((((group * 2 + hl) * 2) + nb) * 8 + ks) * 32 + lane];
    }
    const float* bsrc = group ? b2 : b1;
    float2 bv[2];
    #pragma unroll
    for (int nb = 0; nb < 2; nb++)
        bv[nb] = *(const float2*)(bsrc + 16 * wl + 8 * nb + 2 * tg);

    int ntiles = (n + TM - 1) / TM;
    int bid = blockIdx.x;
    int ntl = (bid < ntiles) ? ((ntiles - 1 - bid) / gridDim.x + 1) : 0;

    #pragma unroll 1
    for (int it = 0; it <= ntl; it++) {
        int buf = it & 1;

        // ---- convert tile t=it (both groups, half each) ----
        if (it < ntl) {
            int row0 = (bid + it * gridDim.x) * TM;
            #pragma unroll 4
            for (int it2 = 0; it2 < 8; it2++) {
                int i = gt + (group * 8 + it2) * 256;
                int row = i >> 5;
                int c4 = i & 31;
                float4 v = make_float4(0.f, 0.f, 0.f, 0.f);
                if (row0 + row < n)
                    v = *(const float4*)(h_in + (size_t)(row0 + row) * H + c4 * 4);
                __nv_bfloat16 hx = __float2bfloat16(v.x), hy = __float2bfloat16(v.y);
                __nv_bfloat16 hz = __float2bfloat16(v.z), hw = __float2bfloat16(v.w);
                int base = row * ROWSTRIDE;
                int p0 = pidx(2 * c4), p1 = pidx(2 * c4 + 1);
                Hs_hi[base + p0] = pack_bf16(__bfloat162float(hx), __bfloat162float(hy));
                Hs_hi[base + p1] = pack_bf16(__bfloat162float(hz), __bfloat162float(hw));
                Hs_lo[base + p0] = pack_bf16(v.x - __bfloat162float(hx), v.y - __bfloat162float(hy));
                Hs_lo[base + p1] = pack_bf16(v.z - __bfloat162float(hz), v.w - __bfloat162float(hw));
            }
        }
        __syncthreads();

        if (group == 0) {
            if (it < ntl) {
                // ---- GEMM1 + silu -> Ts[buf] ----
                uint32_t* Ts_hi = sm + (2 + 2 * buf) * TILE_U32;
                uint32_t* Ts_lo = Ts_hi + TILE_U32;
                #pragma unroll 1
                for (int mb = 0; mb < 8; mb++) {
                    float acc[2][4] = {{0.f, 0.f, 0.f, 0.f}, {0.f, 0.f, 0.f, 0.f}};
                    int ra = (mb * 16 + gid) * ROWSTRIDE;
                    int rb = ra + 8 * ROWSTRIDE;
                    #pragma unroll
                    for (int ks = 0; ks < 8; ks++) {
                        uint2 ah  = *(const uint2*)(Hs_hi + ra + ks * 8 + tg * 2);
                        uint2 ahb = *(const uint2*)(Hs_hi + rb + ks * 8 + tg * 2);
                        uint2 al  = *(const uint2*)(Hs_lo + ra + ks * 8 + tg * 2);
                        uint2 alb = *(const uint2*)(Hs_lo + rb + ks * 8 + tg * 2);
                        #pragma unroll
                        for (int nb = 0; nb < 2; nb++) {
                            uint2 bh = wB[0][nb][ks];
                            uint2 bl = wB[1][nb][ks];
                            MMA_BF16(acc[nb], ah.x, ahb.x, ah.y, ahb.y, bh.x, bh.y);
                            MMA_BF16(acc[nb], al.x, alb.x, al.y, alb.y, bh.x, bh.y);
                            MMA_BF16(acc[nb], ah.x, ahb.x, ah.y, ahb.y, bl.x, bl.y);
                        }
                    }
                    int sa = (mb * 16 + gid) * ROWSTRIDE + 8 * wl + 2 * tg;
                    int sb = sa + 8 * ROWSTRIDE;
                    #pragma unroll
                    for (int nb = 0; nb < 2; nb++) {
                        float f0 = silu_fast(acc[nb][0] + bv[nb].x);
                        float f1 = silu_fast(acc[nb][1] + bv[nb].y);
                        float f2 = silu_fast(acc[nb][2] + bv[nb].x);
                        float f3 = silu_fast(acc[nb][3] + bv[nb].y);
                        __nv_bfloat16 h0 = __float2bfloat16(f0), h1 = __float2bfloat16(f1);
                        __nv_bfloat16 h2 = __float2bfloat16(f2), h3 = __float2bfloat16(f3);
                        Ts_hi[sa + nb] = pack_bf16(__bfloat162float(h0), __bfloat162float(h1));
                        Ts_hi[sb + nb] = pack_bf16(__bfloat162float(h2), __bfloat162float(h3));
                        Ts_lo[sa + nb] = pack_bf16(f0 - __bfloat162float(h0), f1 - __bfloat162float(h1));
                        Ts_lo[sb + nb] = pack_bf16(f2 - __bfloat162float(h2), f3 - __bfloat162float(h3));
                    }
                }
            }
        } else {
            if (it > 0) {
                int row0 = (bid + (it - 1) * gridDim.x) * TM;
                uint32_t* Ts_hi = sm + (2 + 2 * (buf ^ 1)) * TILE_U32;
                uint32_t* Ts_lo = Ts_hi + TILE_U32;
                #pragma unroll 1
                for (int mb = 0; mb < 8; mb++) {
                    float acc[2][4] = {{0.f, 0.f, 0.f, 0.f}, {0.f, 0.f, 0.f, 0.f}};
                    int ra = (mb * 16 + gid) * ROWSTRIDE;
                    int rb = ra + 8 * ROWSTRIDE;
                    #pragma unroll
                    for (int ks = 0; ks < 8; ks++) {
                        uint2 ah  = *(const uint2*)(Ts_hi + ra + ks * 8 + tg * 2);
                        uint2 ahb = *(const uint2*)(Ts_hi + rb + ks * 8 + tg * 2);
                        uint2 al  = *(const uint2*)(Ts_lo + ra + ks * 8 + tg * 2);
                        uint2 alb = *(const uint2*)(Ts_lo + rb + ks * 8 + tg * 2);
                        #pragma unroll
                        for (int nb = 0; nb < 2; nb++) {
                            uint2 bh = wB[0][nb][ks];
                            uint2 bl = wB[1][nb][ks];
                            MMA_BF16(acc[nb], ah.x, ahb.x, ah.y, ahb.y, bh.x, bh.y);
                            MMA_BF16(acc[nb], al.x, alb.x, al.y, alb.y, bh.x, bh.y);
                            MMA_BF16(acc[nb], ah.x, ahb.x, ah.y, ahb.y, bl.x, bl.y);
                        }
                    }
                    int r0 = row0 + mb * 16 + gid;
                    int r1 = r0 + 8;
                    #pragma unroll
                    for (int nb = 0; nb < 2; nb++) {
                        int col = 16 * wl + 8 * nb + 2 * tg;
                        if (r0 < n) {
                            float2 o0 = make_float2(acc[nb][0] + bv[nb].x,
                                                    acc[nb][1] + bv[nb].y);
                            *(float2*)(x_out + (size_t)r0 * H + col) = o0;
                            if (h_out) *(float2*)(h_out + (size_t)r0 * H + col) = o0;
                        }
                        if (r1 < n) {
                            float2 o1 = make_float2(acc[nb][2] + bv[nb].x,
                                                    acc[nb][3] + bv[nb].y);
                            *(float2*)(x_out + (size_t)r1 * H + col) = o1;
                            if (h_out) *(float2*)(h_out + (size_t)r1 * H + col) = o1;
                        }
                    }
                }
            }
        }
        __syncthreads();
    }
}

// batch_vec -> float tail of the output
__global__ void batch_kernel(const int* __restrict__ bv, float* __restrict__ out, int n) {
    int i = blockIdx.x * blockDim.x + threadIdx.x;
    if (i < n) out[i] = (float)bv[i];
}

extern "C" void kernel_launch(void* const* d_in, const int* in_sizes, int n_in,
                              void* d_out, int out_size) {
    const float* emb       = (const float*)d_in[0];
    const float* We        = (const float*)d_in[1];
    const float* be        = (const float*)d_in[2];
    const float* W1        = (const float*)d_in[3];
    const float* b1        = (const float*)d_in[4];
    const float* W2        = (const float*)d_in[5];
    const float* b2        = (const float*)d_in[6];
    const float* edge_attr = (const float*)d_in[7];
    const int*   z         = (const int*)d_in[8];
    const int*   ei        = (const int*)d_in[9];
    const int*   bv        = (const int*)d_in[10];

    int n = in_sizes[8];
    int E = in_sizes[9] / 2;
    float* out = (float*)d_out;

    float *gx, *gh;
    uint32_t* gwf;
    cudaGetSymbolAddress((void**)&gx, g_x);
    cudaGetSymbolAddress((void**)&gh, g_h);
    cudaGetSymbolAddress((void**)&gwf, g_wfrag);

    cudaFuncSetAttribute(mlp_kernel, cudaFuncAttributeMaxDynamicSharedMemorySize,
                         MLP_SMEM);

    int nembed = (n * 32 + 255) / 256;
    int nwprep = (WPREP_TOTAL + 255) / 256;
    prep_kernel<<<nembed + nwprep, 256>>>(emb, z, gx, gh, n, nembed, W1, W2);

    for (int l = 0; l < 3; l++) {
        edge_kernel<<<4096, 256>>>(gx, gh, edge_attr, ei,
                                   We + (size_t)l * 4 * H, be + (size_t)l * H, E);
        bool last = (l == 2);
        mlp_kernel<<<148, MLP_THREADS, MLP_SMEM>>>(
            gh,
            gwf + (size_t)l * 8 * 4 * 2 * 8 * 32 * 2,
            b1 + (size_t)l * H, b2 + (size_t)l * H,
            last ? out : gx,
            last ? nullptr : gh,
            n);
    }

    if (out_size >= n * H + n) {
        batch_kernel<<<(n + 255) / 256, 256>>>(bv, out + (size_t)n * H, n);
    }
}